// round 1
// baseline (speedup 1.0000x reference)
#include <cuda_runtime.h>
#include <math.h>

// ---------------- problem constants ----------------
#define BB   2
#define SS   4096
#define HIDN 2048
#define NH   16
#define HD   128
#define CC   256
#define NCC  16
#define MM   (BB*SS)          // 8192
#define QKVN (3*HIDN)         // 6144

// ---------------- device scratch (static, no allocs) ----------------
__device__ float g_qkv   [(size_t)MM * QKVN];            // silu(x@w_qkv)  [8192,6144]
__device__ float g_gate  [(size_t)MM * HIDN];            // sigmoid(x@w_gate)
__device__ float g_attn  [(size_t)MM * HIDN];            // attention output [B,S,H*D]
__device__ float g_kvdelta[(size_t)BB*NH*NCC*HD*HD];     // per-chunk kv contribution
__device__ float g_kvstate[(size_t)BB*NH*NCC*HD*HD];     // kv state entering each chunk

// ---------------- epilogues ----------------
#define EPI_SILU    0
#define EPI_SIGMOID 1
#define EPI_NONE    2

__device__ __forceinline__ float apply_epi(float x, int mode) {
    if (mode == EPI_SILU)    return x / (1.0f + expf(-x));
    if (mode == EPI_SIGMOID) return 1.0f / (1.0f + expf(-x));
    return x;
}

// ---------------- classic fp32 SGEMM: 128x128x16 tile, 8x8 microtile ----------------
// A [M,K] row-major, B [K,N] row-major, C [M,N]. If GMUL, A is multiplied
// elementwise by G (same layout) at load. M,N multiples of 128; K multiple of 16.
template<int EPI, bool GMUL>
__global__ __launch_bounds__(256) void gemm_kernel(
    const float* __restrict__ A, const float* __restrict__ G,
    const float* __restrict__ Bm, float* __restrict__ Cm,
    int M, int N, int K)
{
    __shared__ float As[16][128];   // transposed: As[k][m]
    __shared__ float Bs[16][128];

    const int tid = threadIdx.x;
    const int bm = blockIdx.y * 128;
    const int bn = blockIdx.x * 128;

    const int tr  = tid >> 4;       // 0..15
    const int tc  = tid & 15;       // 0..15
    const int tm0 = tr * 8;
    const int tn0 = tc * 8;

    float acc[8][8];
    #pragma unroll
    for (int i = 0; i < 8; i++)
        #pragma unroll
        for (int j = 0; j < 8; j++) acc[i][j] = 0.0f;

    for (int k0 = 0; k0 < K; k0 += 16) {
        // load A tile (128 rows x 16 k) -> As[k][m]
        #pragma unroll
        for (int it = 0; it < 2; it++) {
            int idx = tid + 256 * it;        // 0..511 float4s
            int row = idx >> 2;              // 0..127
            int kc  = (idx & 3) * 4;         // 0,4,8,12
            const size_t off = (size_t)(bm + row) * K + k0 + kc;
            float4 va = *(const float4*)(A + off);
            if (GMUL) {
                float4 vg = *(const float4*)(G + off);
                va.x *= vg.x; va.y *= vg.y; va.z *= vg.z; va.w *= vg.w;
            }
            As[kc + 0][row] = va.x;
            As[kc + 1][row] = va.y;
            As[kc + 2][row] = va.z;
            As[kc + 3][row] = va.w;
        }
        // load B tile (16 k x 128 n)
        #pragma unroll
        for (int it = 0; it < 2; it++) {
            int idx  = tid + 256 * it;       // 0..511 float4s
            int krow = idx >> 5;             // 0..15
            int nc   = (idx & 31) * 4;       // 0..124
            *(float4*)&Bs[krow][nc] =
                *(const float4*)(Bm + (size_t)(k0 + krow) * N + bn + nc);
        }
        __syncthreads();

        #pragma unroll
        for (int kk = 0; kk < 16; kk++) {
            float a[8], b[8];
            #pragma unroll
            for (int i = 0; i < 8; i++) a[i] = As[kk][tm0 + i];
            #pragma unroll
            for (int j = 0; j < 8; j++) b[j] = Bs[kk][tn0 + j];
            #pragma unroll
            for (int i = 0; i < 8; i++)
                #pragma unroll
                for (int j = 0; j < 8; j++)
                    acc[i][j] = fmaf(a[i], b[j], acc[i][j]);
        }
        __syncthreads();
    }

    // epilogue + store
    #pragma unroll
    for (int i = 0; i < 8; i++) {
        size_t crow = (size_t)(bm + tm0 + i) * N + bn + tn0;
        #pragma unroll
        for (int j = 0; j < 8; j += 4) {
            float4 v;
            v.x = apply_epi(acc[i][j + 0], EPI);
            v.y = apply_epi(acc[i][j + 1], EPI);
            v.z = apply_epi(acc[i][j + 2], EPI);
            v.w = apply_epi(acc[i][j + 3], EPI);
            *(float4*)(Cm + crow + j) = v;
        }
    }
}

// ---------------- kvdelta: per chunk, kvdelta[d][e] = sum_j kdecay[j]*k[j,d]*v[j,e] ----------------
// grid = B*H*NC (blockIdx.x = bh*NC + n), 256 threads, 8x8 microtile over [128,128]
__global__ __launch_bounds__(256) void kvdelta_kernel(const float* __restrict__ slopes)
{
    __shared__ float ks[16][132];
    __shared__ float vs[16][132];

    const int blk = blockIdx.x;
    const int n  = blk % NCC;
    const int bh = blk / NCC;
    const int b  = bh / NH;
    const int h  = bh % NH;
    const float s = slopes[h];

    const int tid = threadIdx.x;
    const int td0 = (tid >> 4) * 8;
    const int te0 = (tid & 15) * 8;

    float acc[8][8];
    #pragma unroll
    for (int i = 0; i < 8; i++)
        #pragma unroll
        for (int j = 0; j < 8; j++) acc[i][j] = 0.0f;

    const size_t mbase = (size_t)(b * SS + n * CC) * QKVN;

    for (int jt = 0; jt < 16; jt++) {
        #pragma unroll
        for (int it = 0; it < 2; it++) {
            int idx = tid + 256 * it;
            int jj  = idx >> 5;              // 0..15
            int c   = (idx & 31) * 4;        // 0..124
            int j   = jt * 16 + jj;
            float kd = expf(-s * (float)(CC - 1 - j));
            const size_t row = mbase + (size_t)j * QKVN;
            float4 k4 = *(const float4*)(&g_qkv[row + HIDN + h * HD + c]);
            k4.x *= kd; k4.y *= kd; k4.z *= kd; k4.w *= kd;
            *(float4*)&ks[jj][c] = k4;
            *(float4*)&vs[jj][c] = *(const float4*)(&g_qkv[row + 2 * HIDN + h * HD + c]);
        }
        __syncthreads();
        #pragma unroll
        for (int jj = 0; jj < 16; jj++) {
            float a[8], bb[8];
            #pragma unroll
            for (int p = 0; p < 8; p++) a[p]  = ks[jj][td0 + p];
            #pragma unroll
            for (int q = 0; q < 8; q++) bb[q] = vs[jj][te0 + q];
            #pragma unroll
            for (int p = 0; p < 8; p++)
                #pragma unroll
                for (int q = 0; q < 8; q++)
                    acc[p][q] = fmaf(a[p], bb[q], acc[p][q]);
        }
        __syncthreads();
    }

    float* out = &g_kvdelta[(size_t)blk * HD * HD];
    #pragma unroll
    for (int p = 0; p < 8; p++) {
        size_t orow = (size_t)(td0 + p) * HD + te0;
        #pragma unroll
        for (int q = 0; q < 8; q += 4) {
            *(float4*)(&out[orow + q]) =
                make_float4(acc[p][q], acc[p][q+1], acc[p][q+2], acc[p][q+3]);
        }
    }
}

// ---------------- scan: kvstate[n] = bd*kvstate[n-1] + kvdelta[n-1], kvstate[0]=0 ----------------
// grid = B*H (32 blocks), 256 threads
__global__ __launch_bounds__(256) void scan_kernel(const float* __restrict__ slopes)
{
    const int bh = blockIdx.x;
    const int h  = bh % NH;
    const float bd = expf(-slopes[h] * (float)CC);
    const int tid = threadIdx.x;
    const size_t base = (size_t)bh * NCC * HD * HD;

    for (int r = 0; r < 64; r++) {
        int p = tid + 256 * r;               // 0..16383
        float st = 0.0f;
        #pragma unroll
        for (int nn = 0; nn < NCC; nn++) {
            g_kvstate[base + (size_t)nn * HD * HD + p] = st;
            st = bd * st + g_kvdelta[base + (size_t)nn * HD * HD + p];
        }
    }
}

// ---------------- fused intra + inter chunk output ----------------
// grid = B*H*NC*2 (2 i-tiles of 128 per chunk), 256 threads
// o[i,d] = sum_{j<=i} exp(-s(i-j)) (q_i.k_j) v[j,d]  +  qdecay[i] * sum_e q[i,e] kvstate[e,d]
__global__ __launch_bounds__(256) void attn_kernel(const float* __restrict__ slopes)
{
    extern __shared__ float sm[];
    float* qs  = sm;                          // [128][128]
    float* kts = qs  + 128 * 128;             // k transposed [128][17]
    float* vs  = kts + 128 * 17;              // [16][132]
    float* ss  = vs  + 16 * 132;              // score tile [16][136]

    const int blk   = blockIdx.x;
    const int itile = blk & 1;
    const int cn    = blk >> 1;               // bh*NC + n
    const int n  = cn % NCC;
    const int bh = cn / NCC;
    const int b  = bh / NH;
    const int h  = bh % NH;
    const float s = slopes[h];

    const int tid = threadIdx.x;
    const int i0  = itile * 128;
    const size_t mbase = (size_t)(b * SS + n * CC) * QKVN;

    // load q tile (raw)
    #pragma unroll
    for (int it = 0; it < 16; it++) {
        int idx = tid + 256 * it;             // 0..4095 float4s
        int row = idx >> 5;                   // 0..127
        int c   = (idx & 31) * 4;
        *(float4*)&qs[row * 128 + c] =
            *(const float4*)(&g_qkv[mbase + (size_t)(i0 + row) * QKVN + h * HD + c]);
    }
    __syncthreads();

    const int tm0 = (tid >> 4) * 8;           // output rows (i)
    const int tn0 = (tid & 15) * 8;           // output cols (d)
    const int sjj = tid & 15;                 // score-thread j
    const int sig = (tid >> 4) * 8;           // score-thread i base

    float acc[8][8];
    #pragma unroll
    for (int i = 0; i < 8; i++)
        #pragma unroll
        for (int j = 0; j < 8; j++) acc[i][j] = 0.0f;

    const float f = expf(-s);

    // ---- intra-chunk (causal, decayed) ----
    const int njt = i0 / 16 + 8;              // j-tiles with any j <= i_max
    for (int jt = 0; jt < njt; jt++) {
        #pragma unroll
        for (int it = 0; it < 2; it++) {
            int idx = tid + 256 * it;
            int jj  = idx >> 5;
            int c   = (idx & 31) * 4;
            const size_t row = mbase + (size_t)(jt * 16 + jj) * QKVN;
            float4 k4 = *(const float4*)(&g_qkv[row + HIDN + h * HD + c]);
            kts[(c + 0) * 17 + jj] = k4.x;
            kts[(c + 1) * 17 + jj] = k4.y;
            kts[(c + 2) * 17 + jj] = k4.z;
            kts[(c + 3) * 17 + jj] = k4.w;
            *(float4*)&vs[jj * 132 + c] =
                *(const float4*)(&g_qkv[row + 2 * HIDN + h * HD + c]);
        }
        __syncthreads();

        // scores for (sjj, sig..sig+7)
        float dot[8];
        #pragma unroll
        for (int p = 0; p < 8; p++) dot[p] = 0.0f;
        for (int d = 0; d < 128; d++) {
            float kv_ = kts[d * 17 + sjj];
            #pragma unroll
            for (int p = 0; p < 8; p++)
                dot[p] = fmaf(qs[(sig + p) * 128 + d], kv_, dot[p]);
        }
        const int d0 = i0 + sig - (jt * 16 + sjj);
        float cur = (d0 > 0) ? expf(-s * (float)d0) : 1.0f;
        #pragma unroll
        for (int p = 0; p < 8; p++) {
            int di = d0 + p;
            float dec = (di >= 0) ? cur : 0.0f;
            if (di >= 0) cur *= f;
            ss[sjj * 136 + sig + p] = dot[p] * dec;
        }
        __syncthreads();

        // acc += ss^T @ vs
        #pragma unroll
        for (int jj = 0; jj < 16; jj++) {
            float a[8], bb[8];
            #pragma unroll
            for (int p = 0; p < 8; p++) a[p]  = ss[jj * 136 + tm0 + p];
            #pragma unroll
            for (int q = 0; q < 8; q++) bb[q] = vs[jj * 132 + tn0 + q];
            #pragma unroll
            for (int p = 0; p < 8; p++)
                #pragma unroll
                for (int q = 0; q < 8; q++)
                    acc[p][q] = fmaf(a[p], bb[q], acc[p][q]);
        }
        __syncthreads();
    }

    // ---- inter-chunk: acc += (q * qdecay) @ kvstate ----
    const float* kvst = &g_kvstate[((size_t)bh * NCC + n) * HD * HD];
    float qd[8];
    #pragma unroll
    for (int p = 0; p < 8; p++)
        qd[p] = expf(-s * (float)(i0 + sig + p + 1));

    for (int et = 0; et < 8; et++) {
        #pragma unroll
        for (int it = 0; it < 2; it++) {
            int idx = tid + 256 * it;
            int ee  = idx >> 5;
            int c   = (idx & 31) * 4;
            *(float4*)&vs[ee * 132 + c] =
                *(const float4*)(&kvst[(size_t)(et * 16 + ee) * HD + c]);
        }
        // ss[ee][ii] = q[ii][et*16+ee] * qdecay[ii]
        #pragma unroll
        for (int p = 0; p < 8; p++)
            ss[sjj * 136 + sig + p] = qs[(sig + p) * 128 + et * 16 + sjj] * qd[p];
        __syncthreads();

        #pragma unroll
        for (int jj = 0; jj < 16; jj++) {
            float a[8], bb[8];
            #pragma unroll
            for (int p = 0; p < 8; p++) a[p]  = ss[jj * 136 + tm0 + p];
            #pragma unroll
            for (int q = 0; q < 8; q++) bb[q] = vs[jj * 132 + tn0 + q];
            #pragma unroll
            for (int p = 0; p < 8; p++)
                #pragma unroll
                for (int q = 0; q < 8; q++)
                    acc[p][q] = fmaf(a[p], bb[q], acc[p][q]);
        }
        __syncthreads();
    }

    // store to g_attn in [B,S,H*D] layout
    #pragma unroll
    for (int p = 0; p < 8; p++) {
        size_t orow = (size_t)(b * SS + n * CC + i0 + tm0 + p) * HIDN + h * HD + tn0;
        *(float4*)(&g_attn[orow])     = make_float4(acc[p][0], acc[p][1], acc[p][2], acc[p][3]);
        *(float4*)(&g_attn[orow + 4]) = make_float4(acc[p][4], acc[p][5], acc[p][6], acc[p][7]);
    }
}

// ---------------- launch ----------------
extern "C" void kernel_launch(void* const* d_in, const int* in_sizes, int n_in,
                              void* d_out, int out_size)
{
    const float* x      = (const float*)d_in[0];
    const float* w_qkv  = (const float*)d_in[1];
    const float* w_gate = (const float*)d_in[2];
    const float* w_out  = (const float*)d_in[3];
    const float* slopes = (const float*)d_in[4];
    float* out = (float*)d_out;

    float *qkv_p, *gate_p, *attn_p;
    cudaGetSymbolAddress((void**)&qkv_p,  g_qkv);
    cudaGetSymbolAddress((void**)&gate_p, g_gate);
    cudaGetSymbolAddress((void**)&attn_p, g_attn);

    // opt-in dynamic smem for attn kernel (~90KB), idempotent
    static int smem_sz = (128*128 + 128*17 + 16*132 + 16*136) * (int)sizeof(float);
    cudaFuncSetAttribute(attn_kernel, cudaFuncAttributeMaxDynamicSharedMemorySize, smem_sz);

    // 1) qkv = silu(x @ w_qkv)
    {
        dim3 grid(QKVN / 128, MM / 128);
        gemm_kernel<EPI_SILU, false><<<grid, 256>>>(x, nullptr, w_qkv, qkv_p, MM, QKVN, HIDN);
    }
    // 2) gate = sigmoid(x @ w_gate)
    {
        dim3 grid(HIDN / 128, MM / 128);
        gemm_kernel<EPI_SIGMOID, false><<<grid, 256>>>(x, nullptr, w_gate, gate_p, MM, HIDN, HIDN);
    }
    // 3) per-chunk kv deltas
    kvdelta_kernel<<<BB * NH * NCC, 256>>>(slopes);
    // 4) recurrent scan of kv states
    scan_kernel<<<BB * NH, 256>>>(slopes);
    // 5) intra + inter chunk outputs
    attn_kernel<<<BB * NH * NCC * 2, 256, smem_sz>>>(slopes);
    // 6) out = (gate * attn) @ w_out
    {
        dim3 grid(HIDN / 128, MM / 128);
        gemm_kernel<EPI_NONE, true><<<grid, 256>>>(attn_p, gate_p, w_out, out, MM, HIDN, HIDN);
    }
}

// round 3
// speedup vs baseline: 2.4078x; 2.4078x over previous
#include <cuda_runtime.h>
#include <cuda_bf16.h>
#include <math.h>
#include <stdint.h>

// ---------------- problem constants ----------------
#define BB   2
#define SS   4096
#define HIDN 2048
#define NH   16
#define HD   128
#define CC   256
#define NCC  16
#define MM   (BB*SS)          // 8192
#define QKVN (3*HIDN)         // 6144
#define GK   HIDN             // all GEMM K dims = 2048
#define BKC  64               // K per chunk
#define NCHUNK (GK/BKC)       // 32

// ---------------- device scratch (static, no allocs) ----------------
__device__ float g_qkv   [(size_t)MM * QKVN];
__device__ float g_gate  [(size_t)MM * HIDN];
__device__ float g_attn  [(size_t)MM * HIDN];
__device__ float g_kvdelta[(size_t)BB*NH*NCC*HD*HD];
__device__ float g_kvstate[(size_t)BB*NH*NCC*HD*HD];

__device__ __nv_bfloat16 g_xhi[(size_t)MM*HIDN],        g_xlo[(size_t)MM*HIDN];
__device__ __nv_bfloat16 g_wqkvT_hi[(size_t)QKVN*HIDN], g_wqkvT_lo[(size_t)QKVN*HIDN];
__device__ __nv_bfloat16 g_wgateT_hi[(size_t)HIDN*HIDN],g_wgateT_lo[(size_t)HIDN*HIDN];
__device__ __nv_bfloat16 g_woutT_hi[(size_t)HIDN*HIDN], g_woutT_lo[(size_t)HIDN*HIDN];
__device__ __nv_bfloat16 g_gahi[(size_t)MM*HIDN],       g_galo[(size_t)MM*HIDN];

// ---------------- epilogues ----------------
#define EPI_SILU    0
#define EPI_SIGMOID 1
#define EPI_NONE    2

__device__ __forceinline__ float apply_epi(float x, int mode) {
    if (mode == EPI_SILU)    return x / (1.0f + expf(-x));
    if (mode == EPI_SIGMOID) return 1.0f / (1.0f + expf(-x));
    return x;
}

// ---------------- base-ISA tensor-core helpers (sm_80+, valid on sm_103) ----------------
__device__ __forceinline__ uint32_t smem_u32(const void* p) {
    uint32_t a;
    asm("{ .reg .u64 t; cvta.to.shared.u64 t, %1; cvt.u32.u64 %0, t; }" : "=r"(a) : "l"(p));
    return a;
}
__device__ __forceinline__ void cpasync16(uint32_t saddr, const void* g) {
    asm volatile("cp.async.cg.shared.global [%0], [%1], 16;" :: "r"(saddr), "l"(g));
}
__device__ __forceinline__ void cp_commit() {
    asm volatile("cp.async.commit_group;" ::: "memory");
}
template<int N> __device__ __forceinline__ void cp_wait() {
    asm volatile("cp.async.wait_group %0;" :: "n"(N) : "memory");
}
__device__ __forceinline__ void ldm_x4(uint32_t* r, uint32_t addr) {
    asm volatile("ldmatrix.sync.aligned.m8n8.x4.shared.b16 {%0,%1,%2,%3}, [%4];"
                 : "=r"(r[0]), "=r"(r[1]), "=r"(r[2]), "=r"(r[3]) : "r"(addr));
}
__device__ __forceinline__ void ldm_x2(uint32_t* r, uint32_t addr) {
    asm volatile("ldmatrix.sync.aligned.m8n8.x2.shared.b16 {%0,%1}, [%2];"
                 : "=r"(r[0]), "=r"(r[1]) : "r"(addr));
}
__device__ __forceinline__ void mma16816(float* c, const uint32_t* a, const uint32_t* b) {
    asm volatile(
        "mma.sync.aligned.m16n8k16.row.col.f32.bf16.bf16.f32 "
        "{%0,%1,%2,%3},{%4,%5,%6,%7},{%8,%9},{%0,%1,%2,%3};"
        : "+f"(c[0]), "+f"(c[1]), "+f"(c[2]), "+f"(c[3])
        : "r"(a[0]), "r"(a[1]), "r"(a[2]), "r"(a[3]), "r"(b[0]), "r"(b[1]));
}

// ---------------- HMMA split-bf16 GEMM ----------------
// C[M,N] = A[M,K] @ B^T  (A: [M,K] hi/lo bf16, B stored [N,K] hi/lo bf16)
// CTA tile 128x128x64, 8 warps (2Mx4N), warp tile 64x32, 3 precision passes.
// smem per buffer: Ahi/Alo/Bhi/Blo each 128 rows x 72 bf16 (144B stride) = 18432B
#define LDSW   144                        // bytes per smem row (64 bf16 + 8 pad)
#define MATSZ  (128 * LDSW)               // 18432
#define BUFSZ  (4 * MATSZ)                // 73728
#define GEMM_SMEM (2 * BUFSZ)             // 147456

template<int EPI, bool GMUL>
__global__ __launch_bounds__(256) void mma_gemm(
    const __nv_bfloat16* __restrict__ Ahi, const __nv_bfloat16* __restrict__ Alo,
    const __nv_bfloat16* __restrict__ Bhi, const __nv_bfloat16* __restrict__ Blo,
    const float* __restrict__ Gm,          // optional gate multiplier on C (unused here)
    float* __restrict__ C, int M, int N)
{
    extern __shared__ char smraw[];
    const uint32_t sb = smem_u32(smraw);

    const int tid  = threadIdx.x;
    const int lane = tid & 31;
    const int wid  = tid >> 5;
    const int bm = blockIdx.y * 128;
    const int bn = blockIdx.x * 128;
    const int wm = (wid >> 2) * 64;       // 0 / 64
    const int wn = (wid & 3) * 32;        // 0..96

    // per-thread gmem/smem load coords: 1024 16B-sectors per matrix, 4 per thread
    const int lrow = tid >> 3;            // base row 0..31 step handled by iter
    const int lsec = tid & 7;             // 16B sector in row

    // prefetch one chunk into buffer `buf`
    auto prefetch = [&](int c, int buf) {
        const uint32_t bbase = sb + buf * BUFSZ;
        const int k0 = c * BKC;
        #pragma unroll
        for (int i = 0; i < 4; ++i) {
            const int row = lrow + 32 * i;
            const uint32_t so = row * LDSW + lsec * 16;
            const size_t ga = (size_t)(bm + row) * GK + k0 + lsec * 8;
            const size_t gb = (size_t)(bn + row) * GK + k0 + lsec * 8;
            cpasync16(bbase + 0 * MATSZ + so, Ahi + ga);
            cpasync16(bbase + 1 * MATSZ + so, Alo + ga);
            cpasync16(bbase + 2 * MATSZ + so, Bhi + gb);
            cpasync16(bbase + 3 * MATSZ + so, Blo + gb);
        }
        cp_commit();
    };

    float acc[4][4][4];
    #pragma unroll
    for (int mi = 0; mi < 4; ++mi)
        #pragma unroll
        for (int ni = 0; ni < 4; ++ni)
            #pragma unroll
            for (int r = 0; r < 4; ++r) acc[mi][ni][r] = 0.0f;

    // fragment smem address bases (within a matrix)
    const uint32_t aOff = (uint32_t)(wm + (lane & 15)) * LDSW + (lane >> 4) * 16;
    const uint32_t bOff = (uint32_t)(wn + (lane & 7))  * LDSW + ((lane >> 3) & 1) * 16;

    prefetch(0, 0);

    for (int c = 0; c < NCHUNK; ++c) {
        const int cur = c & 1;
        if (c + 1 < NCHUNK) prefetch(c + 1, cur ^ 1);
        if (c + 1 < NCHUNK) cp_wait<1>(); else cp_wait<0>();
        __syncthreads();

        const uint32_t bbase = sb + cur * BUFSZ;
        #pragma unroll
        for (int ks = 0; ks < 4; ++ks) {
            const uint32_t kso = ks * 32;
            uint32_t aH[4][4], aL[4][4], bH[4][2], bL[4][2];
            #pragma unroll
            for (int mi = 0; mi < 4; ++mi) {
                ldm_x4(aH[mi], bbase + 0 * MATSZ + aOff + mi * 16 * LDSW + kso);
                ldm_x4(aL[mi], bbase + 1 * MATSZ + aOff + mi * 16 * LDSW + kso);
            }
            #pragma unroll
            for (int ni = 0; ni < 4; ++ni) {
                ldm_x2(bH[ni], bbase + 2 * MATSZ + bOff + ni * 8 * LDSW + kso);
                ldm_x2(bL[ni], bbase + 3 * MATSZ + bOff + ni * 8 * LDSW + kso);
            }
            #pragma unroll
            for (int mi = 0; mi < 4; ++mi)
                #pragma unroll
                for (int ni = 0; ni < 4; ++ni)
                    mma16816(acc[mi][ni], aH[mi], bH[ni]);
            #pragma unroll
            for (int mi = 0; mi < 4; ++mi)
                #pragma unroll
                for (int ni = 0; ni < 4; ++ni)
                    mma16816(acc[mi][ni], aH[mi], bL[ni]);
            #pragma unroll
            for (int mi = 0; mi < 4; ++mi)
                #pragma unroll
                for (int ni = 0; ni < 4; ++ni)
                    mma16816(acc[mi][ni], aL[mi], bH[ni]);
        }
        __syncthreads();
    }

    // epilogue: c0/c1 -> (row, col), c2/c3 -> (row+8, col); col = 2*(lane&3)
    const int erow = lane >> 2;
    const int ecol = 2 * (lane & 3);
    #pragma unroll
    for (int mi = 0; mi < 4; ++mi) {
        #pragma unroll
        for (int ni = 0; ni < 4; ++ni) {
            const int gr0 = bm + wm + mi * 16 + erow;
            const int gc  = bn + wn + ni * 8 + ecol;
            float2 v0, v1;
            v0.x = apply_epi(acc[mi][ni][0], EPI);
            v0.y = apply_epi(acc[mi][ni][1], EPI);
            v1.x = apply_epi(acc[mi][ni][2], EPI);
            v1.y = apply_epi(acc[mi][ni][3], EPI);
            *(float2*)(C + (size_t)gr0 * N + gc)       = v0;
            *(float2*)(C + (size_t)(gr0 + 8) * N + gc) = v1;
        }
    }
    (void)Gm;
}

// ---------------- conversion kernels ----------------
__global__ __launch_bounds__(256) void split_kernel(
    const float* __restrict__ in, __nv_bfloat16* __restrict__ hi,
    __nv_bfloat16* __restrict__ lo, int n4)
{
    int i = blockIdx.x * 256 + threadIdx.x;
    if (i >= n4) return;
    float4 v = ((const float4*)in)[i];
    float vv[4] = {v.x, v.y, v.z, v.w};
    __nv_bfloat16 h[4], l[4];
    #pragma unroll
    for (int j = 0; j < 4; j++) {
        h[j] = __float2bfloat16(vv[j]);
        l[j] = __float2bfloat16(vv[j] - __bfloat162float(h[j]));
    }
    __nv_bfloat162* H = (__nv_bfloat162*)hi;
    __nv_bfloat162* L = (__nv_bfloat162*)lo;
    H[2 * i]     = __halves2bfloat162(h[0], h[1]);
    H[2 * i + 1] = __halves2bfloat162(h[2], h[3]);
    L[2 * i]     = __halves2bfloat162(l[0], l[1]);
    L[2 * i + 1] = __halves2bfloat162(l[2], l[3]);
}

__global__ __launch_bounds__(256) void mulsplit_kernel(
    const float* __restrict__ a, const float* __restrict__ b,
    __nv_bfloat16* __restrict__ hi, __nv_bfloat16* __restrict__ lo, int n4)
{
    int i = blockIdx.x * 256 + threadIdx.x;
    if (i >= n4) return;
    float4 va = ((const float4*)a)[i];
    float4 vb = ((const float4*)b)[i];
    float vv[4] = {va.x * vb.x, va.y * vb.y, va.z * vb.z, va.w * vb.w};
    __nv_bfloat16 h[4], l[4];
    #pragma unroll
    for (int j = 0; j < 4; j++) {
        h[j] = __float2bfloat16(vv[j]);
        l[j] = __float2bfloat16(vv[j] - __bfloat162float(h[j]));
    }
    __nv_bfloat162* H = (__nv_bfloat162*)hi;
    __nv_bfloat162* L = (__nv_bfloat162*)lo;
    H[2 * i]     = __halves2bfloat162(h[0], h[1]);
    H[2 * i + 1] = __halves2bfloat162(h[2], h[3]);
    L[2 * i]     = __halves2bfloat162(l[0], l[1]);
    L[2 * i + 1] = __halves2bfloat162(l[2], l[3]);
}

// w [K,N] fp32 -> wT hi/lo [N,K] bf16
__global__ __launch_bounds__(256) void transp_split_kernel(
    const float* __restrict__ w, __nv_bfloat16* __restrict__ thi,
    __nv_bfloat16* __restrict__ tlo, int K, int N)
{
    __shared__ float t[32][33];
    const int n0 = blockIdx.x * 32, k0 = blockIdx.y * 32;
    const int x = threadIdx.x, y = threadIdx.y;   // 32 x 8
    #pragma unroll
    for (int r = 0; r < 32; r += 8)
        t[y + r][x] = w[(size_t)(k0 + y + r) * N + n0 + x];
    __syncthreads();
    #pragma unroll
    for (int r = 0; r < 32; r += 8) {
        float v = t[x][y + r];
        __nv_bfloat16 h = __float2bfloat16(v);
        __nv_bfloat16 l = __float2bfloat16(v - __bfloat162float(h));
        size_t o = (size_t)(n0 + y + r) * K + k0 + x;
        thi[o] = h;
        tlo[o] = l;
    }
}

// ---------------- kvdelta (fp32) ----------------
__global__ __launch_bounds__(256) void kvdelta_kernel(const float* __restrict__ slopes)
{
    __shared__ float ks[16][132];
    __shared__ float vs[16][132];

    const int blk = blockIdx.x;
    const int n  = blk % NCC;
    const int bh = blk / NCC;
    const int b  = bh / NH;
    const int h  = bh % NH;
    const float s = slopes[h];

    const int tid = threadIdx.x;
    const int td0 = (tid >> 4) * 8;
    const int te0 = (tid & 15) * 8;

    float acc[8][8];
    #pragma unroll
    for (int i = 0; i < 8; i++)
        #pragma unroll
        for (int j = 0; j < 8; j++) acc[i][j] = 0.0f;

    const size_t mbase = (size_t)(b * SS + n * CC) * QKVN;

    for (int jt = 0; jt < 16; jt++) {
        #pragma unroll
        for (int it = 0; it < 2; it++) {
            int idx = tid + 256 * it;
            int jj  = idx >> 5;
            int c   = (idx & 31) * 4;
            int j   = jt * 16 + jj;
            float kd = expf(-s * (float)(CC - 1 - j));
            const size_t row = mbase + (size_t)j * QKVN;
            float4 k4 = *(const float4*)(&g_qkv[row + HIDN + h * HD + c]);
            k4.x *= kd; k4.y *= kd; k4.z *= kd; k4.w *= kd;
            *(float4*)&ks[jj][c] = k4;
            *(float4*)&vs[jj][c] = *(const float4*)(&g_qkv[row + 2 * HIDN + h * HD + c]);
        }
        __syncthreads();
        #pragma unroll
        for (int jj = 0; jj < 16; jj++) {
            float a[8], bb[8];
            #pragma unroll
            for (int p = 0; p < 8; p++) a[p]  = ks[jj][td0 + p];
            #pragma unroll
            for (int q = 0; q < 8; q++) bb[q] = vs[jj][te0 + q];
            #pragma unroll
            for (int p = 0; p < 8; p++)
                #pragma unroll
                for (int q = 0; q < 8; q++)
                    acc[p][q] = fmaf(a[p], bb[q], acc[p][q]);
        }
        __syncthreads();
    }

    float* out = &g_kvdelta[(size_t)blk * HD * HD];
    #pragma unroll
    for (int p = 0; p < 8; p++) {
        size_t orow = (size_t)(td0 + p) * HD + te0;
        #pragma unroll
        for (int q = 0; q < 8; q += 4) {
            *(float4*)(&out[orow + q]) =
                make_float4(acc[p][q], acc[p][q+1], acc[p][q+2], acc[p][q+3]);
        }
    }
}

// ---------------- scan (parallel: 2048 blocks) ----------------
__global__ __launch_bounds__(256) void scan_kernel(const float* __restrict__ slopes)
{
    const int gid = blockIdx.x * 256 + threadIdx.x;
    const int bh  = gid >> 14;
    const int p   = gid & 16383;
    const float bd = expf(-slopes[bh & (NH - 1)] * (float)CC);
    const size_t base = (size_t)bh * NCC * HD * HD + p;

    float st = 0.0f;
    #pragma unroll
    for (int nn = 0; nn < NCC; nn++) {
        g_kvstate[base + (size_t)nn * HD * HD] = st;
        st = bd * st + g_kvdelta[base + (size_t)nn * HD * HD];
    }
}

// ---------------- fused intra + inter chunk output (fp32) ----------------
__global__ __launch_bounds__(256) void attn_kernel(const float* __restrict__ slopes)
{
    extern __shared__ float sm[];
    float* qs  = sm;
    float* kts = qs  + 128 * 128;
    float* vs  = kts + 128 * 17;
    float* ss  = vs  + 16 * 132;

    const int blk   = blockIdx.x;
    const int itile = blk & 1;
    const int cn    = blk >> 1;
    const int n  = cn % NCC;
    const int bh = cn / NCC;
    const int b  = bh / NH;
    const int h  = bh % NH;
    const float s = slopes[h];

    const int tid = threadIdx.x;
    const int i0  = itile * 128;
    const size_t mbase = (size_t)(b * SS + n * CC) * QKVN;

    #pragma unroll
    for (int it = 0; it < 16; it++) {
        int idx = tid + 256 * it;
        int row = idx >> 5;
        int c   = (idx & 31) * 4;
        *(float4*)&qs[row * 128 + c] =
            *(const float4*)(&g_qkv[mbase + (size_t)(i0 + row) * QKVN + h * HD + c]);
    }
    __syncthreads();

    const int tm0 = (tid >> 4) * 8;
    const int tn0 = (tid & 15) * 8;
    const int sjj = tid & 15;
    const int sig = (tid >> 4) * 8;

    float acc[8][8];
    #pragma unroll
    for (int i = 0; i < 8; i++)
        #pragma unroll
        for (int j = 0; j < 8; j++) acc[i][j] = 0.0f;

    const float f = expf(-s);

    const int njt = i0 / 16 + 8;
    for (int jt = 0; jt < njt; jt++) {
        #pragma unroll
        for (int it = 0; it < 2; it++) {
            int idx = tid + 256 * it;
            int jj  = idx >> 5;
            int c   = (idx & 31) * 4;
            const size_t row = mbase + (size_t)(jt * 16 + jj) * QKVN;
            float4 k4 = *(const float4*)(&g_qkv[row + HIDN + h * HD + c]);
            kts[(c + 0) * 17 + jj] = k4.x;
            kts[(c + 1) * 17 + jj] = k4.y;
            kts[(c + 2) * 17 + jj] = k4.z;
            kts[(c + 3) * 17 + jj] = k4.w;
            *(float4*)&vs[jj * 132 + c] =
                *(const float4*)(&g_qkv[row + 2 * HIDN + h * HD + c]);
        }
        __syncthreads();

        float dot[8];
        #pragma unroll
        for (int p = 0; p < 8; p++) dot[p] = 0.0f;
        for (int d = 0; d < 128; d++) {
            float kv_ = kts[d * 17 + sjj];
            #pragma unroll
            for (int p = 0; p < 8; p++)
                dot[p] = fmaf(qs[(sig + p) * 128 + d], kv_, dot[p]);
        }
        const int d0 = i0 + sig - (jt * 16 + sjj);
        float cur = (d0 > 0) ? expf(-s * (float)d0) : 1.0f;
        #pragma unroll
        for (int p = 0; p < 8; p++) {
            int di = d0 + p;
            float dec = (di >= 0) ? cur : 0.0f;
            if (di >= 0) cur *= f;
            ss[sjj * 136 + sig + p] = dot[p] * dec;
        }
        __syncthreads();

        #pragma unroll
        for (int jj = 0; jj < 16; jj++) {
            float a[8], bb[8];
            #pragma unroll
            for (int p = 0; p < 8; p++) a[p]  = ss[jj * 136 + tm0 + p];
            #pragma unroll
            for (int q = 0; q < 8; q++) bb[q] = vs[jj * 132 + tn0 + q];
            #pragma unroll
            for (int p = 0; p < 8; p++)
                #pragma unroll
                for (int q = 0; q < 8; q++)
                    acc[p][q] = fmaf(a[p], bb[q], acc[p][q]);
        }
        __syncthreads();
    }

    const float* kvst = &g_kvstate[((size_t)bh * NCC + n) * HD * HD];
    float qd[8];
    #pragma unroll
    for (int p = 0; p < 8; p++)
        qd[p] = expf(-s * (float)(i0 + sig + p + 1));

    for (int et = 0; et < 8; et++) {
        #pragma unroll
        for (int it = 0; it < 2; it++) {
            int idx = tid + 256 * it;
            int ee  = idx >> 5;
            int c   = (idx & 31) * 4;
            *(float4*)&vs[ee * 132 + c] =
                *(const float4*)(&kvst[(size_t)(et * 16 + ee) * HD + c]);
        }
        #pragma unroll
        for (int p = 0; p < 8; p++)
            ss[sjj * 136 + sig + p] = qs[(sig + p) * 128 + et * 16 + sjj] * qd[p];
        __syncthreads();

        #pragma unroll
        for (int jj = 0; jj < 16; jj++) {
            float a[8], bb[8];
            #pragma unroll
            for (int p = 0; p < 8; p++) a[p]  = ss[jj * 136 + tm0 + p];
            #pragma unroll
            for (int q = 0; q < 8; q++) bb[q] = vs[jj * 132 + tn0 + q];
            #pragma unroll
            for (int p = 0; p < 8; p++)
                #pragma unroll
                for (int q = 0; q < 8; q++)
                    acc[p][q] = fmaf(a[p], bb[q], acc[p][q]);
        }
        __syncthreads();
    }

    #pragma unroll
    for (int p = 0; p < 8; p++) {
        size_t orow = (size_t)(b * SS + n * CC + i0 + tm0 + p) * HIDN + h * HD + tn0;
        *(float4*)(&g_attn[orow])     = make_float4(acc[p][0], acc[p][1], acc[p][2], acc[p][3]);
        *(float4*)(&g_attn[orow + 4]) = make_float4(acc[p][4], acc[p][5], acc[p][6], acc[p][7]);
    }
}

// ---------------- launch ----------------
extern "C" void kernel_launch(void* const* d_in, const int* in_sizes, int n_in,
                              void* d_out, int out_size)
{
    const float* x      = (const float*)d_in[0];
    const float* w_qkv  = (const float*)d_in[1];
    const float* w_gate = (const float*)d_in[2];
    const float* w_out  = (const float*)d_in[3];
    const float* slopes = (const float*)d_in[4];
    float* out = (float*)d_out;

    float *qkv_p, *gate_p, *attn_p;
    cudaGetSymbolAddress((void**)&qkv_p,  g_qkv);
    cudaGetSymbolAddress((void**)&gate_p, g_gate);
    cudaGetSymbolAddress((void**)&attn_p, g_attn);

    __nv_bfloat16 *xhi, *xlo, *wqh, *wql, *wgh, *wgl, *woh, *wol, *gah, *gal;
    cudaGetSymbolAddress((void**)&xhi, g_xhi);
    cudaGetSymbolAddress((void**)&xlo, g_xlo);
    cudaGetSymbolAddress((void**)&wqh, g_wqkvT_hi);
    cudaGetSymbolAddress((void**)&wql, g_wqkvT_lo);
    cudaGetSymbolAddress((void**)&wgh, g_wgateT_hi);
    cudaGetSymbolAddress((void**)&wgl, g_wgateT_lo);
    cudaGetSymbolAddress((void**)&woh, g_woutT_hi);
    cudaGetSymbolAddress((void**)&wol, g_woutT_lo);
    cudaGetSymbolAddress((void**)&gah, g_gahi);
    cudaGetSymbolAddress((void**)&gal, g_galo);

    static int attn_smem = (128*128 + 128*17 + 16*132 + 16*136) * (int)sizeof(float);
    cudaFuncSetAttribute(attn_kernel, cudaFuncAttributeMaxDynamicSharedMemorySize, attn_smem);
    cudaFuncSetAttribute(mma_gemm<EPI_SILU, false>,
                         cudaFuncAttributeMaxDynamicSharedMemorySize, GEMM_SMEM);
    cudaFuncSetAttribute(mma_gemm<EPI_SIGMOID, false>,
                         cudaFuncAttributeMaxDynamicSharedMemorySize, GEMM_SMEM);
    cudaFuncSetAttribute(mma_gemm<EPI_NONE, false>,
                         cudaFuncAttributeMaxDynamicSharedMemorySize, GEMM_SMEM);

    // 0) precision splits + weight transposes
    {
        int n4 = MM * HIDN / 4;
        split_kernel<<<n4 / 256, 256>>>(x, xhi, xlo, n4);
        dim3 blk(32, 8);
        transp_split_kernel<<<dim3(QKVN / 32, HIDN / 32), blk>>>(w_qkv,  wqh, wql, HIDN, QKVN);
        transp_split_kernel<<<dim3(HIDN / 32, HIDN / 32), blk>>>(w_gate, wgh, wgl, HIDN, HIDN);
        transp_split_kernel<<<dim3(HIDN / 32, HIDN / 32), blk>>>(w_out,  woh, wol, HIDN, HIDN);
    }
    // 1) qkv = silu(x @ w_qkv)
    mma_gemm<EPI_SILU, false><<<dim3(QKVN / 128, MM / 128), 256, GEMM_SMEM>>>(
        xhi, xlo, wqh, wql, nullptr, qkv_p, MM, QKVN);
    // 2) gate = sigmoid(x @ w_gate)
    mma_gemm<EPI_SIGMOID, false><<<dim3(HIDN / 128, MM / 128), 256, GEMM_SMEM>>>(
        xhi, xlo, wgh, wgl, nullptr, gate_p, MM, HIDN);
    // 3) attention pipeline (fp32)
    kvdelta_kernel<<<BB * NH * NCC, 256>>>(slopes);
    scan_kernel<<<BB * NH * 64, 256>>>(slopes);
    attn_kernel<<<BB * NH * NCC * 2, 256, attn_smem>>>(slopes);
    // 4) ga = gate * attn, split
    {
        int n4 = MM * HIDN / 4;
        mulsplit_kernel<<<n4 / 256, 256>>>(gate_p, attn_p, gah, gal, n4);
    }
    // 5) out = ga @ w_out
    mma_gemm<EPI_NONE, false><<<dim3(HIDN / 128, MM / 128), 256, GEMM_SMEM>>>(
        gah, gal, woh, wol, nullptr, out, MM, HIDN);
}

// round 6
// speedup vs baseline: 2.6204x; 1.0883x over previous
#include <cuda_runtime.h>
#include <cuda_bf16.h>
#include <math.h>
#include <stdint.h>

// ---------------- problem constants ----------------
#define BB   2
#define SS   4096
#define HIDN 2048
#define NH   16
#define HD   128
#define CC   256
#define NCC  16
#define MM   (BB*SS)          // 8192
#define QKVN (3*HIDN)         // 6144
#define GK   HIDN
#define BKC  64
#define NCHUNK (GK/BKC)       // 32

// ---------------- device scratch ----------------
__device__ float g_qkv   [(size_t)MM * QKVN];
__device__ float g_gate  [(size_t)MM * HIDN];
__device__ float g_attn  [(size_t)MM * HIDN];
__device__ float g_kvdelta[(size_t)BB*NH*NCC*HD*HD];
__device__ float g_kvstate[(size_t)BB*NH*NCC*HD*HD];

__device__ __nv_bfloat16 g_xhi[(size_t)MM*HIDN],        g_xlo[(size_t)MM*HIDN];
__device__ __nv_bfloat16 g_wqkvT_hi[(size_t)QKVN*HIDN], g_wqkvT_lo[(size_t)QKVN*HIDN];
__device__ __nv_bfloat16 g_wgateT_hi[(size_t)HIDN*HIDN],g_wgateT_lo[(size_t)HIDN*HIDN];
__device__ __nv_bfloat16 g_woutT_hi[(size_t)HIDN*HIDN], g_woutT_lo[(size_t)HIDN*HIDN];
__device__ __nv_bfloat16 g_gahi[(size_t)MM*HIDN],       g_galo[(size_t)MM*HIDN];

#define PHSZ ((size_t)BB*NH*SS*HD)
__device__ __nv_bfloat16 g_q_hi [PHSZ], g_q_lo [PHSZ];    // [bh][s][d]
__device__ __nv_bfloat16 g_qd_hi[PHSZ], g_qd_lo[PHSZ];    // [bh][s][d]
__device__ __nv_bfloat16 g_k_hi [PHSZ], g_k_lo [PHSZ];    // [bh][s][d]
__device__ __nv_bfloat16 g_kdT_hi[PHSZ], g_kdT_lo[PHSZ];  // [bh][d][s]
__device__ __nv_bfloat16 g_vT_hi [PHSZ], g_vT_lo [PHSZ];  // [bh][d][s]
__device__ __nv_bfloat16 g_kvsT_hi[(size_t)BB*NH*NCC*HD*HD], g_kvsT_lo[(size_t)BB*NH*NCC*HD*HD]; // [bhn][e][d']
__device__ float g_qdectab[NH*CC], g_kdectab[NH*CC];

// ---------------- epilogues ----------------
#define EPI_SILU    0
#define EPI_SIGMOID 1
#define EPI_NONE    2

__device__ __forceinline__ float apply_epi(float x, int mode) {
    if (mode == EPI_SILU)    return x / (1.0f + expf(-x));
    if (mode == EPI_SIGMOID) return 1.0f / (1.0f + expf(-x));
    return x;
}

// ---------------- base-ISA tensor-core helpers ----------------
__device__ __forceinline__ uint32_t smem_u32(const void* p) {
    uint32_t a;
    asm("{ .reg .u64 t; cvta.to.shared.u64 t, %1; cvt.u32.u64 %0, t; }" : "=r"(a) : "l"(p));
    return a;
}
__device__ __forceinline__ void cpasync16(uint32_t saddr, const void* g) {
    asm volatile("cp.async.cg.shared.global [%0], [%1], 16;" :: "r"(saddr), "l"(g));
}
__device__ __forceinline__ void cp_commit() {
    asm volatile("cp.async.commit_group;" ::: "memory");
}
template<int N> __device__ __forceinline__ void cp_wait() {
    asm volatile("cp.async.wait_group %0;" :: "n"(N) : "memory");
}
__device__ __forceinline__ void ldm_x4(uint32_t* r, uint32_t addr) {
    asm volatile("ldmatrix.sync.aligned.m8n8.x4.shared.b16 {%0,%1,%2,%3}, [%4];"
                 : "=r"(r[0]), "=r"(r[1]), "=r"(r[2]), "=r"(r[3]) : "r"(addr));
}
__device__ __forceinline__ void ldm_x2(uint32_t* r, uint32_t addr) {
    asm volatile("ldmatrix.sync.aligned.m8n8.x2.shared.b16 {%0,%1}, [%2];"
                 : "=r"(r[0]), "=r"(r[1]) : "r"(addr));
}
__device__ __forceinline__ void mma16816(float* c, const uint32_t* a, const uint32_t* b) {
    asm volatile(
        "mma.sync.aligned.m16n8k16.row.col.f32.bf16.bf16.f32 "
        "{%0,%1,%2,%3},{%4,%5,%6,%7},{%8,%9},{%0,%1,%2,%3};"
        : "+f"(c[0]), "+f"(c[1]), "+f"(c[2]), "+f"(c[3])
        : "r"(a[0]), "r"(a[1]), "r"(a[2]), "r"(a[3]), "r"(b[0]), "r"(b[1]));
}

// ---------------- HMMA split-bf16 GEMM (validated, unchanged) ----------------
#define LDSW   144
#define MATSZ  (128 * LDSW)
#define BUFSZ  (4 * MATSZ)
#define GEMM_SMEM (2 * BUFSZ)

template<int EPI>
__global__ __launch_bounds__(256) void mma_gemm(
    const __nv_bfloat16* __restrict__ Ahi, const __nv_bfloat16* __restrict__ Alo,
    const __nv_bfloat16* __restrict__ Bhi, const __nv_bfloat16* __restrict__ Blo,
    float* __restrict__ C, int M, int N)
{
    extern __shared__ char smraw[];
    const uint32_t sb = smem_u32(smraw);

    const int tid  = threadIdx.x;
    const int lane = tid & 31;
    const int wid  = tid >> 5;
    const int bm = blockIdx.y * 128;
    const int bn = blockIdx.x * 128;
    const int wm = (wid >> 2) * 64;
    const int wn = (wid & 3) * 32;

    const int lrow = tid >> 3;
    const int lsec = tid & 7;

    auto prefetch = [&](int c, int buf) {
        const uint32_t bbase = sb + buf * BUFSZ;
        const int k0 = c * BKC;
        #pragma unroll
        for (int i = 0; i < 4; ++i) {
            const int row = lrow + 32 * i;
            const uint32_t so = row * LDSW + lsec * 16;
            const size_t ga = (size_t)(bm + row) * GK + k0 + lsec * 8;
            const size_t gb = (size_t)(bn + row) * GK + k0 + lsec * 8;
            cpasync16(bbase + 0 * MATSZ + so, Ahi + ga);
            cpasync16(bbase + 1 * MATSZ + so, Alo + ga);
            cpasync16(bbase + 2 * MATSZ + so, Bhi + gb);
            cpasync16(bbase + 3 * MATSZ + so, Blo + gb);
        }
        cp_commit();
    };

    float acc[4][4][4];
    #pragma unroll
    for (int mi = 0; mi < 4; ++mi)
        #pragma unroll
        for (int ni = 0; ni < 4; ++ni)
            #pragma unroll
            for (int r = 0; r < 4; ++r) acc[mi][ni][r] = 0.0f;

    const uint32_t aOff = (uint32_t)(wm + (lane & 15)) * LDSW + (lane >> 4) * 16;
    const uint32_t bOff = (uint32_t)(wn + (lane & 7))  * LDSW + ((lane >> 3) & 1) * 16;

    prefetch(0, 0);

    for (int c = 0; c < NCHUNK; ++c) {
        const int cur = c & 1;
        if (c + 1 < NCHUNK) prefetch(c + 1, cur ^ 1);
        if (c + 1 < NCHUNK) cp_wait<1>(); else cp_wait<0>();
        __syncthreads();

        const uint32_t bbase = sb + cur * BUFSZ;
        #pragma unroll
        for (int ks = 0; ks < 4; ++ks) {
            const uint32_t kso = ks * 32;
            uint32_t aH[4][4], aL[4][4], bH[4][2], bL[4][2];
            #pragma unroll
            for (int mi = 0; mi < 4; ++mi) {
                ldm_x4(aH[mi], bbase + 0 * MATSZ + aOff + mi * 16 * LDSW + kso);
                ldm_x4(aL[mi], bbase + 1 * MATSZ + aOff + mi * 16 * LDSW + kso);
            }
            #pragma unroll
            for (int ni = 0; ni < 4; ++ni) {
                ldm_x2(bH[ni], bbase + 2 * MATSZ + bOff + ni * 8 * LDSW + kso);
                ldm_x2(bL[ni], bbase + 3 * MATSZ + bOff + ni * 8 * LDSW + kso);
            }
            #pragma unroll
            for (int mi = 0; mi < 4; ++mi)
                #pragma unroll
                for (int ni = 0; ni < 4; ++ni)
                    mma16816(acc[mi][ni], aH[mi], bH[ni]);
            #pragma unroll
            for (int mi = 0; mi < 4; ++mi)
                #pragma unroll
                for (int ni = 0; ni < 4; ++ni)
                    mma16816(acc[mi][ni], aH[mi], bL[ni]);
            #pragma unroll
            for (int mi = 0; mi < 4; ++mi)
                #pragma unroll
                for (int ni = 0; ni < 4; ++ni)
                    mma16816(acc[mi][ni], aL[mi], bH[ni]);
        }
        __syncthreads();
    }

    const int erow = lane >> 2;
    const int ecol = 2 * (lane & 3);
    #pragma unroll
    for (int mi = 0; mi < 4; ++mi) {
        #pragma unroll
        for (int ni = 0; ni < 4; ++ni) {
            const int gr0 = bm + wm + mi * 16 + erow;
            const int gc  = bn + wn + ni * 8 + ecol;
            float2 v0, v1;
            v0.x = apply_epi(acc[mi][ni][0], EPI);
            v0.y = apply_epi(acc[mi][ni][1], EPI);
            v1.x = apply_epi(acc[mi][ni][2], EPI);
            v1.y = apply_epi(acc[mi][ni][3], EPI);
            *(float2*)(C + (size_t)gr0 * N + gc)       = v0;
            *(float2*)(C + (size_t)(gr0 + 8) * N + gc) = v1;
        }
    }
}

// ---------------- conversion kernels ----------------
__device__ __forceinline__ void split_store4(
    __nv_bfloat16* hi, __nv_bfloat16* lo, size_t o, float4 v, float scale)
{
    float a[4] = {v.x * scale, v.y * scale, v.z * scale, v.w * scale};
    __nv_bfloat16 h[4], l[4];
    #pragma unroll
    for (int j = 0; j < 4; j++) {
        h[j] = __float2bfloat16(a[j]);
        l[j] = __float2bfloat16(a[j] - __bfloat162float(h[j]));
    }
    *(__nv_bfloat162*)(hi + o)     = __halves2bfloat162(h[0], h[1]);
    *(__nv_bfloat162*)(hi + o + 2) = __halves2bfloat162(h[2], h[3]);
    *(__nv_bfloat162*)(lo + o)     = __halves2bfloat162(l[0], l[1]);
    *(__nv_bfloat162*)(lo + o + 2) = __halves2bfloat162(l[2], l[3]);
}

__global__ __launch_bounds__(256) void split_kernel(
    const float* __restrict__ in, __nv_bfloat16* __restrict__ hi,
    __nv_bfloat16* __restrict__ lo, int n4)
{
    int i = blockIdx.x * 256 + threadIdx.x;
    if (i >= n4) return;
    split_store4(hi, lo, (size_t)i * 4, ((const float4*)in)[i], 1.0f);
}

__global__ __launch_bounds__(256) void mulsplit_kernel(
    const float* __restrict__ a, const float* __restrict__ b,
    __nv_bfloat16* __restrict__ hi, __nv_bfloat16* __restrict__ lo, int n4)
{
    int i = blockIdx.x * 256 + threadIdx.x;
    if (i >= n4) return;
    float4 va = ((const float4*)a)[i];
    float4 vb = ((const float4*)b)[i];
    float4 v = make_float4(va.x * vb.x, va.y * vb.y, va.z * vb.z, va.w * vb.w);
    split_store4(hi, lo, (size_t)i * 4, v, 1.0f);
}

__global__ __launch_bounds__(256) void transp_split_kernel(
    const float* __restrict__ w, __nv_bfloat16* __restrict__ thi,
    __nv_bfloat16* __restrict__ tlo, int K, int N)
{
    __shared__ float t[32][33];
    const int n0 = blockIdx.x * 32, k0 = blockIdx.y * 32;
    const int x = threadIdx.x, y = threadIdx.y;
    #pragma unroll
    for (int r = 0; r < 32; r += 8)
        t[y + r][x] = w[(size_t)(k0 + y + r) * N + n0 + x];
    __syncthreads();
    #pragma unroll
    for (int r = 0; r < 32; r += 8) {
        float v = t[x][y + r];
        __nv_bfloat16 h = __float2bfloat16(v);
        __nv_bfloat16 l = __float2bfloat16(v - __bfloat162float(h));
        size_t o = (size_t)(n0 + y + r) * K + k0 + x;
        thi[o] = h;
        tlo[o] = l;
    }
}

__global__ void dectab_kernel(const float* __restrict__ slopes)
{
    int h = blockIdx.x, i = threadIdx.x;
    float s = slopes[h];
    g_qdectab[h * CC + i] = expf(-s * (float)(i + 1));
    g_kdectab[h * CC + i] = expf(-s * (float)(CC - 1 - i));
}

// g_qkv -> q, qd, k in [bh][s][d] bf16 split
__global__ __launch_bounds__(256) void splitqkv_norm()
{
    int idx = blockIdx.x * 256 + threadIdx.x;
    int d4 = idx & 31; int rest = idx >> 5;
    int h = rest & 15; rest >>= 4;
    int s = rest & 4095; int b = rest >> 12;

    size_t qo = (size_t)(b * SS + s) * QKVN + h * HD + d4 * 4;
    float4 q = *(const float4*)&g_qkv[qo];
    float4 k = *(const float4*)&g_qkv[qo + HIDN];

    float qdec = g_qdectab[h * CC + (s & (CC - 1))];

    size_t o = ((size_t)(b * NH + h) * SS + s) * HD + d4 * 4;
    split_store4(g_q_hi,  g_q_lo,  o, q, 1.0f);
    split_store4(g_qd_hi, g_qd_lo, o, q, qdec);
    split_store4(g_k_hi,  g_k_lo,  o, k, 1.0f);
}

// g_qkv k,v -> kdT, vT in [bh][d][s] bf16 split
__global__ void trans_split_head()
{
    __shared__ float tk[32][33], tv[32][33];
    const int z  = blockIdx.z;
    const int b  = z >> 4, h = z & 15;
    const int s0 = blockIdx.x * 32;
    const int d0 = blockIdx.y * 32;
    const int x = threadIdx.x, y = threadIdx.y;

    #pragma unroll
    for (int r = 0; r < 32; r += 8) {
        size_t base = (size_t)(b * SS + s0 + y + r) * QKVN + h * HD + d0 + x;
        tk[y + r][x] = g_qkv[base + HIDN];
        tv[y + r][x] = g_qkv[base + 2 * HIDN];
    }
    __syncthreads();
    #pragma unroll
    for (int r = 0; r < 32; r += 8) {
        int d = d0 + y + r;
        int s = s0 + x;
        float kdec = g_kdectab[h * CC + (s & (CC - 1))];
        float kv = tk[x][y + r] * kdec;
        float vv = tv[x][y + r];
        size_t o = ((size_t)z * HD + d) * SS + s;
        __nv_bfloat16 h1 = __float2bfloat16(kv);
        g_kdT_hi[o] = h1;
        g_kdT_lo[o] = __float2bfloat16(kv - __bfloat162float(h1));
        __nv_bfloat16 h2 = __float2bfloat16(vv);
        g_vT_hi[o] = h2;
        g_vT_lo[o] = __float2bfloat16(vv - __bfloat162float(h2));
    }
}

// g_kvstate [bhn][d'][e] -> kvsT [bhn][e][d'] bf16 split
__global__ void kvsplitT_kernel()
{
    __shared__ float t[32][33];
    const int bhn = blockIdx.z;
    const int d0 = blockIdx.x * 32;
    const int e0 = blockIdx.y * 32;
    const int x = threadIdx.x, y = threadIdx.y;
    const size_t base = (size_t)bhn * HD * HD;

    #pragma unroll
    for (int r = 0; r < 32; r += 8)
        t[y + r][x] = g_kvstate[base + (size_t)(d0 + y + r) * HD + e0 + x];
    __syncthreads();
    #pragma unroll
    for (int r = 0; r < 32; r += 8) {
        float v = t[x][y + r];
        size_t o = base + (size_t)(e0 + y + r) * HD + d0 + x;
        __nv_bfloat16 h1 = __float2bfloat16(v);
        g_kvsT_hi[o] = h1;
        g_kvsT_lo[o] = __float2bfloat16(v - __bfloat162float(h1));
    }
}

// ---------------- kvdelta via HMMA (non-trans) ----------------
#define KD_AHI 0
#define KD_ALO 18432
#define KD_BHI 36864
#define KD_BLO 55296
#define KD_SMEM 73728

__global__ __launch_bounds__(256) void kvdelta_mma()
{
    extern __shared__ char smraw[];
    const uint32_t sb = smem_u32(smraw);

    const int blk = blockIdx.x;
    const int n  = blk & (NCC - 1);
    const int bh = blk >> 4;
    const size_t colb = (size_t)bh * HD;

    const int tid = threadIdx.x, lane = tid & 31, wid = tid >> 5;
    const int wm = (wid >> 2) * 64;
    const int wn = (wid & 3) * 32;

    float acc[4][4][4];
    #pragma unroll
    for (int mi = 0; mi < 4; ++mi)
        #pragma unroll
        for (int ni = 0; ni < 4; ++ni)
            #pragma unroll
            for (int r = 0; r < 4; ++r) acc[mi][ni][r] = 0.0f;

    for (int kt = 0; kt < 4; ++kt) {
        const int k0 = n * CC + kt * 64;
        // 128 rows x 64 bf16 (128 B) per matrix = 1024 sectors
        #pragma unroll
        for (int it = 0; it < 4; ++it) {
            int idx = tid + 256 * it;
            int row = idx >> 3, sec = idx & 7;
            size_t g = (colb + row) * SS + k0 + sec * 8;
            uint32_t so = row * 144 + sec * 16;
            cpasync16(sb + KD_AHI + so, g_kdT_hi + g);
            cpasync16(sb + KD_ALO + so, g_kdT_lo + g);
            cpasync16(sb + KD_BHI + so, g_vT_hi + g);
            cpasync16(sb + KD_BLO + so, g_vT_lo + g);
        }
        cp_commit();
        cp_wait<0>();
        __syncthreads();

        #pragma unroll
        for (int ks = 0; ks < 4; ++ks) {
            uint32_t aH[4][4], aL[4][4], bH[4][2], bL[4][2];
            const uint32_t ao = (uint32_t)(lane & 15) * 144 + (lane >> 4) * 16 + ks * 32;
            #pragma unroll
            for (int mi = 0; mi < 4; ++mi) {
                ldm_x4(aH[mi], sb + KD_AHI + (wm + mi * 16) * 144 + ao);
                ldm_x4(aL[mi], sb + KD_ALO + (wm + mi * 16) * 144 + ao);
            }
            const uint32_t bo = (uint32_t)(lane & 7) * 144 + ((lane >> 3) & 1) * 16 + ks * 32;
            #pragma unroll
            for (int ni = 0; ni < 4; ++ni) {
                ldm_x2(bH[ni], sb + KD_BHI + (wn + ni * 8) * 144 + bo);
                ldm_x2(bL[ni], sb + KD_BLO + (wn + ni * 8) * 144 + bo);
            }
            #pragma unroll
            for (int mi = 0; mi < 4; ++mi)
                #pragma unroll
                for (int ni = 0; ni < 4; ++ni)
                    mma16816(acc[mi][ni], aH[mi], bH[ni]);
            #pragma unroll
            for (int mi = 0; mi < 4; ++mi)
                #pragma unroll
                for (int ni = 0; ni < 4; ++ni)
                    mma16816(acc[mi][ni], aH[mi], bL[ni]);
            #pragma unroll
            for (int mi = 0; mi < 4; ++mi)
                #pragma unroll
                for (int ni = 0; ni < 4; ++ni)
                    mma16816(acc[mi][ni], aL[mi], bH[ni]);
        }
        __syncthreads();
    }

    const int erow = lane >> 2, ecol = 2 * (lane & 3);
    float* out = &g_kvdelta[(size_t)blk * HD * HD];
    #pragma unroll
    for (int mi = 0; mi < 4; ++mi) {
        #pragma unroll
        for (int ni = 0; ni < 4; ++ni) {
            int d = wm + mi * 16 + erow;
            int e = wn + ni * 8 + ecol;
            *(float2*)(out + (size_t)d * HD + e)       = make_float2(acc[mi][ni][0], acc[mi][ni][1]);
            *(float2*)(out + (size_t)(d + 8) * HD + e) = make_float2(acc[mi][ni][2], acc[mi][ni][3]);
        }
    }
}

// ---------------- scan (parallel) ----------------
__global__ __launch_bounds__(256) void scan_kernel(const float* __restrict__ slopes)
{
    const int gid = blockIdx.x * 256 + threadIdx.x;
    const int bh  = gid >> 14;
    const int p   = gid & 16383;
    const float bd = expf(-slopes[bh & (NH - 1)] * (float)CC);
    const size_t base = (size_t)bh * NCC * HD * HD + p;

    float st = 0.0f;
    #pragma unroll
    for (int nn = 0; nn < NCC; nn++) {
        g_kvstate[base + (size_t)nn * HD * HD] = st;
        st = bd * st + g_kvdelta[base + (size_t)nn * HD * HD];
    }
}

// ---------------- fused attention via HMMA (non-trans) ----------------
#define A_QHI   0
#define A_QLO   34816
#define A_KHI   69632
#define A_KLO   87040
#define A_VTHI  104448
#define A_VTLO  122880
#define A_SHI   141312
#define A_SLO   159744
#define A_SMEM  178176
#define A_KVSHI 69632
#define A_KVSLO 104448

__global__ __launch_bounds__(256) void attn_mma(const float* __restrict__ slopes)
{
    extern __shared__ char smraw[];
    const uint32_t sb = smem_u32(smraw);
    __shared__ float sdec[CC];

    const int blk = blockIdx.x;
    const int itile = blockIdx.y;
    const int n  = blk & (NCC - 1);
    const int bh = blk >> 4;
    const int h  = bh & (NH - 1);
    const int b  = bh >> 4;
    const float s = slopes[h];

    const int tid = threadIdx.x, lane = tid & 31, wid = tid >> 5;
    sdec[tid] = expf(-s * (float)tid);

    const size_t rowb = (size_t)bh * SS + n * CC;
    const size_t colb = (size_t)bh * HD;
    const int i0 = itile * 128;

    // q tile: 128 rows x 128 bf16 (256 B) = 2048 sectors  [FIXED: was 1024]
    #pragma unroll
    for (int it = 0; it < 8; ++it) {
        int idx = tid + 256 * it;
        int row = idx >> 4, sec = idx & 15;
        size_t g = (rowb + i0 + row) * HD + sec * 8;
        uint32_t so = row * 272 + sec * 16;
        cpasync16(sb + A_QHI + so, g_q_hi + g);
        cpasync16(sb + A_QLO + so, g_q_lo + g);
    }
    cp_commit();

    const int wm  = (wid >> 2) * 64;
    const int wns = (wid & 3) * 16;
    const int wno = (wid & 3) * 32;
    const int erow = lane >> 2, ecol = 2 * (lane & 3);

    float oacc[4][4][4];
    #pragma unroll
    for (int mi = 0; mi < 4; ++mi)
        #pragma unroll
        for (int ni = 0; ni < 4; ++ni)
            #pragma unroll
            for (int r = 0; r < 4; ++r) oacc[mi][ni][r] = 0.0f;

    const int njt = 2 * (itile + 1);
    for (int jt = 0; jt < njt; ++jt) {
        const int j0 = jt * 64;
        // k tile: 64 rows x 128 bf16 (256 B) = 1024 sectors  [FIXED: was 512]
        #pragma unroll
        for (int it = 0; it < 4; ++it) {
            int idx = tid + 256 * it;
            int row = idx >> 4, sec = idx & 15;
            size_t g = (rowb + j0 + row) * HD + sec * 8;
            uint32_t so = row * 272 + sec * 16;
            cpasync16(sb + A_KHI + so, g_k_hi + g);
            cpasync16(sb + A_KLO + so, g_k_lo + g);
        }
        // vT tile: 128 rows x 64 bf16 (128 B) = 1024 sectors (correct)
        #pragma unroll
        for (int it = 0; it < 4; ++it) {
            int idx = tid + 256 * it;
            int row = idx >> 3, sec = idx & 7;
            size_t g = (colb + row) * SS + n * CC + j0 + sec * 8;
            uint32_t so = row * 144 + sec * 16;
            cpasync16(sb + A_VTHI + so, g_vT_hi + g);
            cpasync16(sb + A_VTLO + so, g_vT_lo + g);
        }
        cp_commit();
        cp_wait<0>();
        __syncthreads();

        // ---- S = q @ k^T ----
        float sacc[4][2][4];
        #pragma unroll
        for (int mi = 0; mi < 4; ++mi)
            #pragma unroll
            for (int ni = 0; ni < 2; ++ni)
                #pragma unroll
                for (int r = 0; r < 4; ++r) sacc[mi][ni][r] = 0.0f;

        #pragma unroll
        for (int ks = 0; ks < 8; ++ks) {
            uint32_t aH[4][4], aL[4][4], bH[2][2], bL[2][2];
            const uint32_t ao = (uint32_t)(lane & 15) * 272 + (lane >> 4) * 16 + ks * 32;
            #pragma unroll
            for (int mi = 0; mi < 4; ++mi) {
                ldm_x4(aH[mi], sb + A_QHI + (wm + mi * 16) * 272 + ao);
                ldm_x4(aL[mi], sb + A_QLO + (wm + mi * 16) * 272 + ao);
            }
            const uint32_t bo = (uint32_t)(lane & 7) * 272 + ((lane >> 3) & 1) * 16 + ks * 32;
            #pragma unroll
            for (int ni = 0; ni < 2; ++ni) {
                ldm_x2(bH[ni], sb + A_KHI + (wns + ni * 8) * 272 + bo);
                ldm_x2(bL[ni], sb + A_KLO + (wns + ni * 8) * 272 + bo);
            }
            #pragma unroll
            for (int mi = 0; mi < 4; ++mi)
                #pragma unroll
                for (int ni = 0; ni < 2; ++ni)
                    mma16816(sacc[mi][ni], aH[mi], bH[ni]);
            #pragma unroll
            for (int mi = 0; mi < 4; ++mi)
                #pragma unroll
                for (int ni = 0; ni < 2; ++ni)
                    mma16816(sacc[mi][ni], aH[mi], bL[ni]);
            #pragma unroll
            for (int mi = 0; mi < 4; ++mi)
                #pragma unroll
                for (int ni = 0; ni < 2; ++ni)
                    mma16816(sacc[mi][ni], aL[mi], bH[ni]);
        }

        // ---- decay + split S ----
        #pragma unroll
        for (int mi = 0; mi < 4; ++mi) {
            #pragma unroll
            for (int ni = 0; ni < 2; ++ni) {
                #pragma unroll
                for (int r = 0; r < 4; ++r) {
                    int il = wm + mi * 16 + erow + (r >> 1) * 8;
                    int jl = wns + ni * 8 + ecol + (r & 1);
                    int dd = (i0 + il) - (j0 + jl);
                    float val = (dd >= 0) ? sacc[mi][ni][r] * sdec[dd] : 0.0f;
                    __nv_bfloat16 hi = __float2bfloat16(val);
                    __nv_bfloat16 lo = __float2bfloat16(val - __bfloat162float(hi));
                    *(__nv_bfloat16*)(smraw + A_SHI + il * 144 + jl * 2) = hi;
                    *(__nv_bfloat16*)(smraw + A_SLO + il * 144 + jl * 2) = lo;
                }
            }
        }
        __syncthreads();

        // ---- O += S̃ @ v ----
        #pragma unroll
        for (int ks = 0; ks < 4; ++ks) {
            uint32_t aH[4][4], aL[4][4], bH[4][2], bL[4][2];
            const uint32_t ao = (uint32_t)(lane & 15) * 144 + (lane >> 4) * 16 + ks * 32;
            #pragma unroll
            for (int mi = 0; mi < 4; ++mi) {
                ldm_x4(aH[mi], sb + A_SHI + (wm + mi * 16) * 144 + ao);
                ldm_x4(aL[mi], sb + A_SLO + (wm + mi * 16) * 144 + ao);
            }
            const uint32_t bo = (uint32_t)(lane & 7) * 144 + ((lane >> 3) & 1) * 16 + ks * 32;
            #pragma unroll
            for (int ni = 0; ni < 4; ++ni) {
                ldm_x2(bH[ni], sb + A_VTHI + (wno + ni * 8) * 144 + bo);
                ldm_x2(bL[ni], sb + A_VTLO + (wno + ni * 8) * 144 + bo);
            }
            #pragma unroll
            for (int mi = 0; mi < 4; ++mi)
                #pragma unroll
                for (int ni = 0; ni < 4; ++ni)
                    mma16816(oacc[mi][ni], aH[mi], bH[ni]);
            #pragma unroll
            for (int mi = 0; mi < 4; ++mi)
                #pragma unroll
                for (int ni = 0; ni < 4; ++ni)
                    mma16816(oacc[mi][ni], aH[mi], bL[ni]);
            #pragma unroll
            for (int mi = 0; mi < 4; ++mi)
                #pragma unroll
                for (int ni = 0; ni < 4; ++ni)
                    mma16816(oacc[mi][ni], aL[mi], bH[ni]);
        }
        __syncthreads();
    }

    // ---- inter: O += qd @ kvstate ----
    {
        // qd tile: 2048 sectors [FIXED: was 1024]
        #pragma unroll
        for (int it = 0; it < 8; ++it) {
            int idx = tid + 256 * it;
            int row = idx >> 4, sec = idx & 15;
            size_t g = (rowb + i0 + row) * HD + sec * 8;
            uint32_t so = row * 272 + sec * 16;
            cpasync16(sb + A_QHI + so, g_qd_hi + g);
            cpasync16(sb + A_QLO + so, g_qd_lo + g);
        }
        const size_t kvb = (size_t)blk * HD * HD;
        #pragma unroll
        for (int it = 0; it < 8; ++it) {
            int idx = tid + 256 * it;
            int row = idx >> 4, sec = idx & 15;
            size_t g = kvb + (size_t)row * HD + sec * 8;
            uint32_t so = row * 272 + sec * 16;
            cpasync16(sb + A_KVSHI + so, g_kvsT_hi + g);
            cpasync16(sb + A_KVSLO + so, g_kvsT_lo + g);
        }
        cp_commit();
        cp_wait<0>();
        __syncthreads();

        #pragma unroll
        for (int ks = 0; ks < 8; ++ks) {
            uint32_t aH[4][4], aL[4][4], bH[4][2], bL[4][2];
            const uint32_t ao = (uint32_t)(lane & 15) * 272 + (lane >> 4) * 16 + ks * 32;
            #pragma unroll
            for (int mi = 0; mi < 4; ++mi) {
                ldm_x4(aH[mi], sb + A_QHI + (wm + mi * 16) * 272 + ao);
                ldm_x4(aL[mi], sb + A_QLO + (wm + mi * 16) * 272 + ao);
            }
            const uint32_t bo = (uint32_t)(lane & 7) * 272 + ((lane >> 3) & 1) * 16 + ks * 32;
            #pragma unroll
            for (int ni = 0; ni < 4; ++ni) {
                ldm_x2(bH[ni], sb + A_KVSHI + (wno + ni * 8) * 272 + bo);
                ldm_x2(bL[ni], sb + A_KVSLO + (wno + ni * 8) * 272 + bo);
            }
            #pragma unroll
            for (int mi = 0; mi < 4; ++mi)
                #pragma unroll
                for (int ni = 0; ni < 4; ++ni)
                    mma16816(oacc[mi][ni], aH[mi], bH[ni]);
            #pragma unroll
            for (int mi = 0; mi < 4; ++mi)
                #pragma unroll
                for (int ni = 0; ni < 4; ++ni)
                    mma16816(oacc[mi][ni], aH[mi], bL[ni]);
            #pragma unroll
            for (int mi = 0; mi < 4; ++mi)
                #pragma unroll
                for (int ni = 0; ni < 4; ++ni)
                    mma16816(oacc[mi][ni], aL[mi], bH[ni]);
        }
    }

    // ---- epilogue ----
    #pragma unroll
    for (int mi = 0; mi < 4; ++mi) {
        #pragma unroll
        for (int ni = 0; ni < 4; ++ni) {
            int il = wm + mi * 16 + erow;
            int e  = wno + ni * 8 + ecol;
            size_t o0 = (size_t)(b * SS + n * CC + i0 + il) * HIDN + h * HD + e;
            *(float2*)(g_attn + o0)            = make_float2(oacc[mi][ni][0], oacc[mi][ni][1]);
            *(float2*)(g_attn + o0 + 8 * HIDN) = make_float2(oacc[mi][ni][2], oacc[mi][ni][3]);
        }
    }
}

// ---------------- launch ----------------
extern "C" void kernel_launch(void* const* d_in, const int* in_sizes, int n_in,
                              void* d_out, int out_size)
{
    const float* x      = (const float*)d_in[0];
    const float* w_qkv  = (const float*)d_in[1];
    const float* w_gate = (const float*)d_in[2];
    const float* w_out  = (const float*)d_in[3];
    const float* slopes = (const float*)d_in[4];
    float* out = (float*)d_out;

    float *qkv_p, *gate_p, *attn_p;
    cudaGetSymbolAddress((void**)&qkv_p,  g_qkv);
    cudaGetSymbolAddress((void**)&gate_p, g_gate);
    cudaGetSymbolAddress((void**)&attn_p, g_attn);

    __nv_bfloat16 *xhi, *xlo, *wqh, *wql, *wgh, *wgl, *woh, *wol, *gah, *gal;
    cudaGetSymbolAddress((void**)&xhi, g_xhi);
    cudaGetSymbolAddress((void**)&xlo, g_xlo);
    cudaGetSymbolAddress((void**)&wqh, g_wqkvT_hi);
    cudaGetSymbolAddress((void**)&wql, g_wqkvT_lo);
    cudaGetSymbolAddress((void**)&wgh, g_wgateT_hi);
    cudaGetSymbolAddress((void**)&wgl, g_wgateT_lo);
    cudaGetSymbolAddress((void**)&woh, g_woutT_hi);
    cudaGetSymbolAddress((void**)&wol, g_woutT_lo);
    cudaGetSymbolAddress((void**)&gah, g_gahi);
    cudaGetSymbolAddress((void**)&gal, g_galo);

    cudaFuncSetAttribute(mma_gemm<EPI_SILU>,
                         cudaFuncAttributeMaxDynamicSharedMemorySize, GEMM_SMEM);
    cudaFuncSetAttribute(mma_gemm<EPI_SIGMOID>,
                         cudaFuncAttributeMaxDynamicSharedMemorySize, GEMM_SMEM);
    cudaFuncSetAttribute(mma_gemm<EPI_NONE>,
                         cudaFuncAttributeMaxDynamicSharedMemorySize, GEMM_SMEM);
    cudaFuncSetAttribute(attn_mma,
                         cudaFuncAttributeMaxDynamicSharedMemorySize, A_SMEM);
    cudaFuncSetAttribute(kvdelta_mma,
                         cudaFuncAttributeMaxDynamicSharedMemorySize, KD_SMEM);

    // 0) splits + transposes + decay tables
    {
        int n4 = MM * HIDN / 4;
        split_kernel<<<n4 / 256, 256>>>(x, xhi, xlo, n4);
        dim3 blk(32, 8);
        transp_split_kernel<<<dim3(QKVN / 32, HIDN / 32), blk>>>(w_qkv,  wqh, wql, HIDN, QKVN);
        transp_split_kernel<<<dim3(HIDN / 32, HIDN / 32), blk>>>(w_gate, wgh, wgl, HIDN, HIDN);
        transp_split_kernel<<<dim3(HIDN / 32, HIDN / 32), blk>>>(w_out,  woh, wol, HIDN, HIDN);
        dectab_kernel<<<NH, CC>>>(slopes);
    }
    // 1) qkv = silu(x @ w_qkv)
    mma_gemm<EPI_SILU><<<dim3(QKVN / 128, MM / 128), 256, GEMM_SMEM>>>(
        xhi, xlo, wqh, wql, qkv_p, MM, QKVN);
    // 2) per-head splits
    splitqkv_norm<<<(BB * SS * NH * 32) / 256, 256>>>();
    {
        dim3 blk(32, 8);
        trans_split_head<<<dim3(SS / 32, HD / 32, BB * NH), blk>>>();
    }
    // 3) gate = sigmoid(x @ w_gate)
    mma_gemm<EPI_SIGMOID><<<dim3(HIDN / 128, MM / 128), 256, GEMM_SMEM>>>(
        xhi, xlo, wgh, wgl, gate_p, MM, HIDN);
    // 4) attention pipeline
    kvdelta_mma<<<BB * NH * NCC, 256, KD_SMEM>>>();
    scan_kernel<<<BB * NH * 64, 256>>>(slopes);
    {
        dim3 blk(32, 8);
        kvsplitT_kernel<<<dim3(HD / 32, HD / 32, BB * NH * NCC), blk>>>();
    }
    attn_mma<<<dim3(BB * NH * NCC, 2), 256, A_SMEM>>>(slopes);
    // 5) ga = gate * attn
    {
        int n4 = MM * HIDN / 4;
        mulsplit_kernel<<<n4 / 256, 256>>>(gate_p, attn_p, gah, gal, n4);
    }
    // 6) out = ga @ w_out
    mma_gemm<EPI_NONE><<<dim3(HIDN / 128, MM / 128), 256, GEMM_SMEM>>>(
        gah, gal, woh, wol, out, MM, HIDN);
}

// round 7
// speedup vs baseline: 2.6562x; 1.0137x over previous
#include <cuda_runtime.h>
#include <cuda_bf16.h>
#include <math.h>
#include <stdint.h>

// ---------------- problem constants ----------------
#define BB   2
#define SS   4096
#define HIDN 2048
#define NH   16
#define HD   128
#define CC   256
#define NCC  16
#define MM   (BB*SS)          // 8192
#define QKVN (3*HIDN)         // 6144
#define GK   HIDN
#define BKC  64
#define NCHUNK (GK/BKC)       // 32

// ---------------- device scratch ----------------
__device__ float g_qkv   [(size_t)MM * QKVN];
__device__ float g_gate  [(size_t)MM * HIDN];
__device__ float g_kvdelta[(size_t)BB*NH*NCC*HD*HD];
__device__ float g_kvstate[(size_t)BB*NH*NCC*HD*HD];

__device__ __nv_bfloat16 g_xhi[(size_t)MM*HIDN],        g_xlo[(size_t)MM*HIDN];
__device__ __nv_bfloat16 g_wqkvT_hi[(size_t)QKVN*HIDN], g_wqkvT_lo[(size_t)QKVN*HIDN];
__device__ __nv_bfloat16 g_wgateT_hi[(size_t)HIDN*HIDN],g_wgateT_lo[(size_t)HIDN*HIDN];
__device__ __nv_bfloat16 g_woutT_hi[(size_t)HIDN*HIDN], g_woutT_lo[(size_t)HIDN*HIDN];
__device__ __nv_bfloat16 g_gahi[(size_t)MM*HIDN],       g_galo[(size_t)MM*HIDN];

#define PHSZ ((size_t)BB*NH*SS*HD)
__device__ __nv_bfloat16 g_q_hi [PHSZ], g_q_lo [PHSZ];    // [bh][s][d]
__device__ __nv_bfloat16 g_k_hi [PHSZ], g_k_lo [PHSZ];    // [bh][s][d]
__device__ __nv_bfloat16 g_kdT_hi[PHSZ], g_kdT_lo[PHSZ];  // [bh][d][s]
__device__ __nv_bfloat16 g_vT_hi [PHSZ], g_vT_lo [PHSZ];  // [bh][d][s]
__device__ __nv_bfloat16 g_kvsT_hi[(size_t)BB*NH*NCC*HD*HD], g_kvsT_lo[(size_t)BB*NH*NCC*HD*HD]; // [bhn][e][d']
__device__ float g_qdectab[NH*CC], g_kdectab[NH*CC];

// ---------------- epilogues ----------------
#define EPI_SILU    0
#define EPI_SIGMOID 1
#define EPI_NONE    2

__device__ __forceinline__ float apply_epi(float x, int mode) {
    if (mode == EPI_SILU)    return x / (1.0f + expf(-x));
    if (mode == EPI_SIGMOID) return 1.0f / (1.0f + expf(-x));
    return x;
}

// ---------------- base-ISA tensor-core helpers ----------------
__device__ __forceinline__ uint32_t smem_u32(const void* p) {
    uint32_t a;
    asm("{ .reg .u64 t; cvta.to.shared.u64 t, %1; cvt.u32.u64 %0, t; }" : "=r"(a) : "l"(p));
    return a;
}
__device__ __forceinline__ void cpasync16(uint32_t saddr, const void* g) {
    asm volatile("cp.async.cg.shared.global [%0], [%1], 16;" :: "r"(saddr), "l"(g));
}
__device__ __forceinline__ void cp_commit() {
    asm volatile("cp.async.commit_group;" ::: "memory");
}
template<int N> __device__ __forceinline__ void cp_wait() {
    asm volatile("cp.async.wait_group %0;" :: "n"(N) : "memory");
}
__device__ __forceinline__ void ldm_x4(uint32_t* r, uint32_t addr) {
    asm volatile("ldmatrix.sync.aligned.m8n8.x4.shared.b16 {%0,%1,%2,%3}, [%4];"
                 : "=r"(r[0]), "=r"(r[1]), "=r"(r[2]), "=r"(r[3]) : "r"(addr));
}
__device__ __forceinline__ void ldm_x2(uint32_t* r, uint32_t addr) {
    asm volatile("ldmatrix.sync.aligned.m8n8.x2.shared.b16 {%0,%1}, [%2];"
                 : "=r"(r[0]), "=r"(r[1]) : "r"(addr));
}
__device__ __forceinline__ void mma16816(float* c, const uint32_t* a, const uint32_t* b) {
    asm volatile(
        "mma.sync.aligned.m16n8k16.row.col.f32.bf16.bf16.f32 "
        "{%0,%1,%2,%3},{%4,%5,%6,%7},{%8,%9},{%0,%1,%2,%3};"
        : "+f"(c[0]), "+f"(c[1]), "+f"(c[2]), "+f"(c[3])
        : "r"(a[0]), "r"(a[1]), "r"(a[2]), "r"(a[3]), "r"(b[0]), "r"(b[1]));
}

// ---------------- HMMA split-bf16 GEMM (validated, unchanged) ----------------
#define LDSW   144
#define MATSZ  (128 * LDSW)
#define BUFSZ  (4 * MATSZ)
#define GEMM_SMEM (2 * BUFSZ)

template<int EPI>
__global__ __launch_bounds__(256) void mma_gemm(
    const __nv_bfloat16* __restrict__ Ahi, const __nv_bfloat16* __restrict__ Alo,
    const __nv_bfloat16* __restrict__ Bhi, const __nv_bfloat16* __restrict__ Blo,
    float* __restrict__ C, int M, int N)
{
    extern __shared__ char smraw[];
    const uint32_t sb = smem_u32(smraw);

    const int tid  = threadIdx.x;
    const int lane = tid & 31;
    const int wid  = tid >> 5;
    const int bm = blockIdx.y * 128;
    const int bn = blockIdx.x * 128;
    const int wm = (wid >> 2) * 64;
    const int wn = (wid & 3) * 32;

    const int lrow = tid >> 3;
    const int lsec = tid & 7;

    auto prefetch = [&](int c, int buf) {
        const uint32_t bbase = sb + buf * BUFSZ;
        const int k0 = c * BKC;
        #pragma unroll
        for (int i = 0; i < 4; ++i) {
            const int row = lrow + 32 * i;
            const uint32_t so = row * LDSW + lsec * 16;
            const size_t ga = (size_t)(bm + row) * GK + k0 + lsec * 8;
            const size_t gb = (size_t)(bn + row) * GK + k0 + lsec * 8;
            cpasync16(bbase + 0 * MATSZ + so, Ahi + ga);
            cpasync16(bbase + 1 * MATSZ + so, Alo + ga);
            cpasync16(bbase + 2 * MATSZ + so, Bhi + gb);
            cpasync16(bbase + 3 * MATSZ + so, Blo + gb);
        }
        cp_commit();
    };

    float acc[4][4][4];
    #pragma unroll
    for (int mi = 0; mi < 4; ++mi)
        #pragma unroll
        for (int ni = 0; ni < 4; ++ni)
            #pragma unroll
            for (int r = 0; r < 4; ++r) acc[mi][ni][r] = 0.0f;

    const uint32_t aOff = (uint32_t)(wm + (lane & 15)) * LDSW + (lane >> 4) * 16;
    const uint32_t bOff = (uint32_t)(wn + (lane & 7))  * LDSW + ((lane >> 3) & 1) * 16;

    prefetch(0, 0);

    for (int c = 0; c < NCHUNK; ++c) {
        const int cur = c & 1;
        if (c + 1 < NCHUNK) prefetch(c + 1, cur ^ 1);
        if (c + 1 < NCHUNK) cp_wait<1>(); else cp_wait<0>();
        __syncthreads();

        const uint32_t bbase = sb + cur * BUFSZ;
        #pragma unroll
        for (int ks = 0; ks < 4; ++ks) {
            const uint32_t kso = ks * 32;
            uint32_t aH[4][4], aL[4][4], bH[4][2], bL[4][2];
            #pragma unroll
            for (int mi = 0; mi < 4; ++mi) {
                ldm_x4(aH[mi], bbase + 0 * MATSZ + aOff + mi * 16 * LDSW + kso);
                ldm_x4(aL[mi], bbase + 1 * MATSZ + aOff + mi * 16 * LDSW + kso);
            }
            #pragma unroll
            for (int ni = 0; ni < 4; ++ni) {
                ldm_x2(bH[ni], bbase + 2 * MATSZ + bOff + ni * 8 * LDSW + kso);
                ldm_x2(bL[ni], bbase + 3 * MATSZ + bOff + ni * 8 * LDSW + kso);
            }
            #pragma unroll
            for (int mi = 0; mi < 4; ++mi)
                #pragma unroll
                for (int ni = 0; ni < 4; ++ni)
                    mma16816(acc[mi][ni], aH[mi], bH[ni]);
            #pragma unroll
            for (int mi = 0; mi < 4; ++mi)
                #pragma unroll
                for (int ni = 0; ni < 4; ++ni)
                    mma16816(acc[mi][ni], aH[mi], bL[ni]);
            #pragma unroll
            for (int mi = 0; mi < 4; ++mi)
                #pragma unroll
                for (int ni = 0; ni < 4; ++ni)
                    mma16816(acc[mi][ni], aL[mi], bH[ni]);
        }
        __syncthreads();
    }

    const int erow = lane >> 2;
    const int ecol = 2 * (lane & 3);
    #pragma unroll
    for (int mi = 0; mi < 4; ++mi) {
        #pragma unroll
        for (int ni = 0; ni < 4; ++ni) {
            const int gr0 = bm + wm + mi * 16 + erow;
            const int gc  = bn + wn + ni * 8 + ecol;
            float2 v0, v1;
            v0.x = apply_epi(acc[mi][ni][0], EPI);
            v0.y = apply_epi(acc[mi][ni][1], EPI);
            v1.x = apply_epi(acc[mi][ni][2], EPI);
            v1.y = apply_epi(acc[mi][ni][3], EPI);
            *(float2*)(C + (size_t)gr0 * N + gc)       = v0;
            *(float2*)(C + (size_t)(gr0 + 8) * N + gc) = v1;
        }
    }
}

// ---------------- conversion kernels ----------------
__device__ __forceinline__ void split_store4(
    __nv_bfloat16* hi, __nv_bfloat16* lo, size_t o, float4 v, float scale)
{
    float a[4] = {v.x * scale, v.y * scale, v.z * scale, v.w * scale};
    __nv_bfloat16 h[4], l[4];
    #pragma unroll
    for (int j = 0; j < 4; j++) {
        h[j] = __float2bfloat16(a[j]);
        l[j] = __float2bfloat16(a[j] - __bfloat162float(h[j]));
    }
    *(__nv_bfloat162*)(hi + o)     = __halves2bfloat162(h[0], h[1]);
    *(__nv_bfloat162*)(hi + o + 2) = __halves2bfloat162(h[2], h[3]);
    *(__nv_bfloat162*)(lo + o)     = __halves2bfloat162(l[0], l[1]);
    *(__nv_bfloat162*)(lo + o + 2) = __halves2bfloat162(l[2], l[3]);
}

__global__ __launch_bounds__(256) void split_kernel(
    const float* __restrict__ in, __nv_bfloat16* __restrict__ hi,
    __nv_bfloat16* __restrict__ lo, int n4)
{
    int i = blockIdx.x * 256 + threadIdx.x;
    if (i >= n4) return;
    split_store4(hi, lo, (size_t)i * 4, ((const float4*)in)[i], 1.0f);
}

__global__ __launch_bounds__(256) void transp_split_kernel(
    const float* __restrict__ w, __nv_bfloat16* __restrict__ thi,
    __nv_bfloat16* __restrict__ tlo, int K, int N)
{
    __shared__ float t[32][33];
    const int n0 = blockIdx.x * 32, k0 = blockIdx.y * 32;
    const int x = threadIdx.x, y = threadIdx.y;
    #pragma unroll
    for (int r = 0; r < 32; r += 8)
        t[y + r][x] = w[(size_t)(k0 + y + r) * N + n0 + x];
    __syncthreads();
    #pragma unroll
    for (int r = 0; r < 32; r += 8) {
        float v = t[x][y + r];
        __nv_bfloat16 h = __float2bfloat16(v);
        __nv_bfloat16 l = __float2bfloat16(v - __bfloat162float(h));
        size_t o = (size_t)(n0 + y + r) * K + k0 + x;
        thi[o] = h;
        tlo[o] = l;
    }
}

__global__ void dectab_kernel(const float* __restrict__ slopes)
{
    int h = blockIdx.x, i = threadIdx.x;
    float s = slopes[h];
    g_qdectab[h * CC + i] = expf(-s * (float)(i + 1));
    g_kdectab[h * CC + i] = expf(-s * (float)(CC - 1 - i));
}

// g_qkv -> q, k in [bh][s][d] bf16 split
__global__ __launch_bounds__(256) void splitqkv_norm()
{
    int idx = blockIdx.x * 256 + threadIdx.x;
    int d4 = idx & 31; int rest = idx >> 5;
    int h = rest & 15; rest >>= 4;
    int s = rest & 4095; int b = rest >> 12;

    size_t qo = (size_t)(b * SS + s) * QKVN + h * HD + d4 * 4;
    float4 q = *(const float4*)&g_qkv[qo];
    float4 k = *(const float4*)&g_qkv[qo + HIDN];

    size_t o = ((size_t)(b * NH + h) * SS + s) * HD + d4 * 4;
    split_store4(g_q_hi, g_q_lo, o, q, 1.0f);
    split_store4(g_k_hi, g_k_lo, o, k, 1.0f);
}

// g_qkv k,v -> kdT, vT in [bh][d][s] bf16 split
__global__ void trans_split_head()
{
    __shared__ float tk[32][33], tv[32][33];
    const int z  = blockIdx.z;
    const int b  = z >> 4, h = z & 15;
    const int s0 = blockIdx.x * 32;
    const int d0 = blockIdx.y * 32;
    const int x = threadIdx.x, y = threadIdx.y;

    #pragma unroll
    for (int r = 0; r < 32; r += 8) {
        size_t base = (size_t)(b * SS + s0 + y + r) * QKVN + h * HD + d0 + x;
        tk[y + r][x] = g_qkv[base + HIDN];
        tv[y + r][x] = g_qkv[base + 2 * HIDN];
    }
    __syncthreads();
    #pragma unroll
    for (int r = 0; r < 32; r += 8) {
        int d = d0 + y + r;
        int s = s0 + x;
        float kdec = g_kdectab[h * CC + (s & (CC - 1))];
        float kv = tk[x][y + r] * kdec;
        float vv = tv[x][y + r];
        size_t o = ((size_t)z * HD + d) * SS + s;
        __nv_bfloat16 h1 = __float2bfloat16(kv);
        g_kdT_hi[o] = h1;
        g_kdT_lo[o] = __float2bfloat16(kv - __bfloat162float(h1));
        __nv_bfloat16 h2 = __float2bfloat16(vv);
        g_vT_hi[o] = h2;
        g_vT_lo[o] = __float2bfloat16(vv - __bfloat162float(h2));
    }
}

// g_kvstate [bhn][d'][e] -> kvsT [bhn][e][d'] bf16 split
__global__ void kvsplitT_kernel()
{
    __shared__ float t[32][33];
    const int bhn = blockIdx.z;
    const int d0 = blockIdx.x * 32;
    const int e0 = blockIdx.y * 32;
    const int x = threadIdx.x, y = threadIdx.y;
    const size_t base = (size_t)bhn * HD * HD;

    #pragma unroll
    for (int r = 0; r < 32; r += 8)
        t[y + r][x] = g_kvstate[base + (size_t)(d0 + y + r) * HD + e0 + x];
    __syncthreads();
    #pragma unroll
    for (int r = 0; r < 32; r += 8) {
        float v = t[x][y + r];
        size_t o = base + (size_t)(e0 + y + r) * HD + d0 + x;
        __nv_bfloat16 h1 = __float2bfloat16(v);
        g_kvsT_hi[o] = h1;
        g_kvsT_lo[o] = __float2bfloat16(v - __bfloat162float(h1));
    }
}

// ---------------- kvdelta via HMMA (double-buffered) ----------------
#define KD_MAT  18432
#define KD_BUF  (4 * KD_MAT)          // 73728
#define KD_SMEM (2 * KD_BUF)          // 147456

__global__ __launch_bounds__(256) void kvdelta_mma()
{
    extern __shared__ char smraw[];
    const uint32_t sb = smem_u32(smraw);

    const int blk = blockIdx.x;
    const int n  = blk & (NCC - 1);
    const int bh = blk >> 4;
    const size_t colb = (size_t)bh * HD;

    const int tid = threadIdx.x, lane = tid & 31, wid = tid >> 5;
    const int wm = (wid >> 2) * 64;
    const int wn = (wid & 3) * 32;

    auto prefetch = [&](int kt, int buf) {
        const uint32_t bbase = sb + buf * KD_BUF;
        const int k0 = n * CC + kt * 64;
        #pragma unroll
        for (int it = 0; it < 4; ++it) {
            int idx = tid + 256 * it;
            int row = idx >> 3, sec = idx & 7;
            size_t g = (colb + row) * SS + k0 + sec * 8;
            uint32_t so = row * 144 + sec * 16;
            cpasync16(bbase + 0 * KD_MAT + so, g_kdT_hi + g);
            cpasync16(bbase + 1 * KD_MAT + so, g_kdT_lo + g);
            cpasync16(bbase + 2 * KD_MAT + so, g_vT_hi + g);
            cpasync16(bbase + 3 * KD_MAT + so, g_vT_lo + g);
        }
        cp_commit();
    };

    float acc[4][4][4];
    #pragma unroll
    for (int mi = 0; mi < 4; ++mi)
        #pragma unroll
        for (int ni = 0; ni < 4; ++ni)
            #pragma unroll
            for (int r = 0; r < 4; ++r) acc[mi][ni][r] = 0.0f;

    prefetch(0, 0);

    for (int kt = 0; kt < 4; ++kt) {
        const int cur = kt & 1;
        if (kt + 1 < 4) prefetch(kt + 1, cur ^ 1);
        if (kt + 1 < 4) cp_wait<1>(); else cp_wait<0>();
        __syncthreads();

        const uint32_t bbase = sb + cur * KD_BUF;
        #pragma unroll
        for (int ks = 0; ks < 4; ++ks) {
            uint32_t aH[4][4], aL[4][4], bH[4][2], bL[4][2];
            const uint32_t ao = (uint32_t)(lane & 15) * 144 + (lane >> 4) * 16 + ks * 32;
            #pragma unroll
            for (int mi = 0; mi < 4; ++mi) {
                ldm_x4(aH[mi], bbase + 0 * KD_MAT + (wm + mi * 16) * 144 + ao);
                ldm_x4(aL[mi], bbase + 1 * KD_MAT + (wm + mi * 16) * 144 + ao);
            }
            const uint32_t bo = (uint32_t)(lane & 7) * 144 + ((lane >> 3) & 1) * 16 + ks * 32;
            #pragma unroll
            for (int ni = 0; ni < 4; ++ni) {
                ldm_x2(bH[ni], bbase + 2 * KD_MAT + (wn + ni * 8) * 144 + bo);
                ldm_x2(bL[ni], bbase + 3 * KD_MAT + (wn + ni * 8) * 144 + bo);
            }
            #pragma unroll
            for (int mi = 0; mi < 4; ++mi)
                #pragma unroll
                for (int ni = 0; ni < 4; ++ni)
                    mma16816(acc[mi][ni], aH[mi], bH[ni]);
            #pragma unroll
            for (int mi = 0; mi < 4; ++mi)
                #pragma unroll
                for (int ni = 0; ni < 4; ++ni)
                    mma16816(acc[mi][ni], aH[mi], bL[ni]);
            #pragma unroll
            for (int mi = 0; mi < 4; ++mi)
                #pragma unroll
                for (int ni = 0; ni < 4; ++ni)
                    mma16816(acc[mi][ni], aL[mi], bH[ni]);
        }
        __syncthreads();
    }

    const int erow = lane >> 2, ecol = 2 * (lane & 3);
    float* out = &g_kvdelta[(size_t)blk * HD * HD];
    #pragma unroll
    for (int mi = 0; mi < 4; ++mi) {
        #pragma unroll
        for (int ni = 0; ni < 4; ++ni) {
            int d = wm + mi * 16 + erow;
            int e = wn + ni * 8 + ecol;
            *(float2*)(out + (size_t)d * HD + e)       = make_float2(acc[mi][ni][0], acc[mi][ni][1]);
            *(float2*)(out + (size_t)(d + 8) * HD + e) = make_float2(acc[mi][ni][2], acc[mi][ni][3]);
        }
    }
}

// ---------------- scan (parallel) ----------------
__global__ __launch_bounds__(256) void scan_kernel(const float* __restrict__ slopes)
{
    const int gid = blockIdx.x * 256 + threadIdx.x;
    const int bh  = gid >> 14;
    const int p   = gid & 16383;
    const float bd = expf(-slopes[bh & (NH - 1)] * (float)CC);
    const size_t base = (size_t)bh * NCC * HD * HD + p;

    float st = 0.0f;
    #pragma unroll
    for (int nn = 0; nn < NCC; nn++) {
        g_kvstate[base + (size_t)nn * HD * HD] = st;
        st = bd * st + g_kvdelta[base + (size_t)nn * HD * HD];
    }
}

// ---------------- fused attention via HMMA (pipelined, inter-first) ----------------
// layout (bytes):
//  q   hi 0       lo 34816   (128 rows x 272)
//  k   hi 69632   lo 87040   (64 rows x 272)
//  vT  buf0 hi 104448 lo 122880; buf1 hi 141312 lo 159744  (128 rows x 144)
//  S   hi 178176  lo 196608  (128 rows x 144)
//  kvsT (inter only, before j-loop): hi at 69632 (spans k region), lo at 178176 (spans S region)
#define A_QHI   0
#define A_QLO   34816
#define A_KHI   69632
#define A_KLO   87040
#define A_VT0   104448
#define A_VT1   141312
#define A_SHI   178176
#define A_SLO   196608
#define A_SMEM  215040
#define A_KVSHI 69632
#define A_KVSLO 178176

__global__ __launch_bounds__(256) void attn_mma(const float* __restrict__ slopes)
{
    extern __shared__ char smraw[];
    const uint32_t sb = smem_u32(smraw);
    __shared__ float sdec[CC];

    const int blk = blockIdx.x;
    const int itile = blockIdx.y;
    const int n  = blk & (NCC - 1);
    const int bh = blk >> 4;
    const int h  = bh & (NH - 1);
    const int b  = bh >> 4;
    const float s = slopes[h];

    const int tid = threadIdx.x, lane = tid & 31, wid = tid >> 5;
    sdec[tid] = expf(-s * (float)tid);
    const float fexp = expf(-s);

    const size_t rowb = (size_t)bh * SS + n * CC;
    const size_t colb = (size_t)bh * HD;
    const int i0 = itile * 128;

    // group 0: q tile + kvsT (inter operand)
    #pragma unroll
    for (int it = 0; it < 8; ++it) {
        int idx = tid + 256 * it;
        int row = idx >> 4, sec = idx & 15;
        size_t g = (rowb + i0 + row) * HD + sec * 8;
        uint32_t so = row * 272 + sec * 16;
        cpasync16(sb + A_QHI + so, g_q_hi + g);
        cpasync16(sb + A_QLO + so, g_q_lo + g);
    }
    {
        const size_t kvb = (size_t)blk * HD * HD;
        #pragma unroll
        for (int it = 0; it < 8; ++it) {
            int idx = tid + 256 * it;
            int row = idx >> 4, sec = idx & 15;
            size_t g = kvb + (size_t)row * HD + sec * 8;
            uint32_t so = row * 272 + sec * 16;
            cpasync16(sb + A_KVSHI + so, g_kvsT_hi + g);
            cpasync16(sb + A_KVSLO + so, g_kvsT_lo + g);
        }
    }
    cp_commit();

    // group 1: vT(j=0) into buf0 (independent regions — safe to overlap inter)
    #pragma unroll
    for (int it = 0; it < 4; ++it) {
        int idx = tid + 256 * it;
        int row = idx >> 3, sec = idx & 7;
        size_t g = (colb + row) * SS + n * CC + sec * 8;
        uint32_t so = row * 144 + sec * 16;
        cpasync16(sb + A_VT0 + so, g_vT_hi + g);
        cpasync16(sb + A_VT0 + 18432 + so, g_vT_lo + g);
    }
    cp_commit();

    const int wm  = (wid >> 2) * 64;
    const int wns = (wid & 3) * 16;
    const int wno = (wid & 3) * 32;
    const int erow = lane >> 2, ecol = 2 * (lane & 3);

    float oacc[4][4][4];
    #pragma unroll
    for (int mi = 0; mi < 4; ++mi)
        #pragma unroll
        for (int ni = 0; ni < 4; ++ni)
            #pragma unroll
            for (int r = 0; r < 4; ++r) oacc[mi][ni][r] = 0.0f;

    // ---- inter FIRST: oacc = q @ kvsT, then row-scale by qdec ----
    cp_wait<1>();          // group0 (q + kvsT) done; vT0 still in flight
    __syncthreads();

    #pragma unroll
    for (int ks = 0; ks < 8; ++ks) {
        uint32_t aH[4][4], aL[4][4], bH[4][2], bL[4][2];
        const uint32_t ao = (uint32_t)(lane & 15) * 272 + (lane >> 4) * 16 + ks * 32;
        #pragma unroll
        for (int mi = 0; mi < 4; ++mi) {
            ldm_x4(aH[mi], sb + A_QHI + (wm + mi * 16) * 272 + ao);
            ldm_x4(aL[mi], sb + A_QLO + (wm + mi * 16) * 272 + ao);
        }
        const uint32_t bo = (uint32_t)(lane & 7) * 272 + ((lane >> 3) & 1) * 16 + ks * 32;
        #pragma unroll
        for (int ni = 0; ni < 4; ++ni) {
            ldm_x2(bH[ni], sb + A_KVSHI + (wno + ni * 8) * 272 + bo);
            ldm_x2(bL[ni], sb + A_KVSLO + (wno + ni * 8) * 272 + bo);
        }
        #pragma unroll
        for (int mi = 0; mi < 4; ++mi)
            #pragma unroll
            for (int ni = 0; ni < 4; ++ni)
                mma16816(oacc[mi][ni], aH[mi], bH[ni]);
        #pragma unroll
        for (int mi = 0; mi < 4; ++mi)
            #pragma unroll
            for (int ni = 0; ni < 4; ++ni)
                mma16816(oacc[mi][ni], aH[mi], bL[ni]);
        #pragma unroll
        for (int mi = 0; mi < 4; ++mi)
            #pragma unroll
            for (int ni = 0; ni < 4; ++ni)
                mma16816(oacc[mi][ni], aL[mi], bH[ni]);
    }
    // row scale: qdec(i) = exp(-s*(i+1)) = sdec[i] * fexp
    #pragma unroll
    for (int mi = 0; mi < 4; ++mi) {
        const int il0 = wm + mi * 16 + erow;
        const float qd0 = sdec[i0 + il0] * fexp;
        const float qd1 = sdec[i0 + il0 + 8] * fexp;
        #pragma unroll
        for (int ni = 0; ni < 4; ++ni) {
            oacc[mi][ni][0] *= qd0;
            oacc[mi][ni][1] *= qd0;
            oacc[mi][ni][2] *= qd1;
            oacc[mi][ni][3] *= qd1;
        }
    }
    __syncthreads();   // all warps done reading kvsT before k(0) overwrites it

    // load k(0) into k region (group 2)
    #pragma unroll
    for (int it = 0; it < 4; ++it) {
        int idx = tid + 256 * it;
        int row = idx >> 4, sec = idx & 15;
        size_t g = (rowb + row) * HD + sec * 8;
        uint32_t so = row * 272 + sec * 16;
        cpasync16(sb + A_KHI + so, g_k_hi + g);
        cpasync16(sb + A_KLO + so, g_k_lo + g);
    }
    cp_commit();

    // ---- intra j-loop (pipelined) ----
    const int njt = 2 * (itile + 1);
    for (int jt = 0; jt < njt; ++jt) {
        const int j0 = jt * 64;
        const int cur = jt & 1;
        const uint32_t vtb = sb + (cur ? A_VT1 : A_VT0);

        cp_wait<0>();      // k(jt) + vT(jt) ready
        __syncthreads();

        // ---- S = q @ k^T ----
        float sacc[4][2][4];
        #pragma unroll
        for (int mi = 0; mi < 4; ++mi)
            #pragma unroll
            for (int ni = 0; ni < 2; ++ni)
                #pragma unroll
                for (int r = 0; r < 4; ++r) sacc[mi][ni][r] = 0.0f;

        #pragma unroll
        for (int ks = 0; ks < 8; ++ks) {
            uint32_t aH[4][4], aL[4][4], bH[2][2], bL[2][2];
            const uint32_t ao = (uint32_t)(lane & 15) * 272 + (lane >> 4) * 16 + ks * 32;
            #pragma unroll
            for (int mi = 0; mi < 4; ++mi) {
                ldm_x4(aH[mi], sb + A_QHI + (wm + mi * 16) * 272 + ao);
                ldm_x4(aL[mi], sb + A_QLO + (wm + mi * 16) * 272 + ao);
            }
            const uint32_t bo = (uint32_t)(lane & 7) * 272 + ((lane >> 3) & 1) * 16 + ks * 32;
            #pragma unroll
            for (int ni = 0; ni < 2; ++ni) {
                ldm_x2(bH[ni], sb + A_KHI + (wns + ni * 8) * 272 + bo);
                ldm_x2(bL[ni], sb + A_KLO + (wns + ni * 8) * 272 + bo);
            }
            #pragma unroll
            for (int mi = 0; mi < 4; ++mi)
                #pragma unroll
                for (int ni = 0; ni < 2; ++ni)
                    mma16816(sacc[mi][ni], aH[mi], bH[ni]);
            #pragma unroll
            for (int mi = 0; mi < 4; ++mi)
                #pragma unroll
                for (int ni = 0; ni < 2; ++ni)
                    mma16816(sacc[mi][ni], aH[mi], bL[ni]);
            #pragma unroll
            for (int mi = 0; mi < 4; ++mi)
                #pragma unroll
                for (int ni = 0; ni < 2; ++ni)
                    mma16816(sacc[mi][ni], aL[mi], bH[ni]);
        }

        // ---- decay + split S ----
        #pragma unroll
        for (int mi = 0; mi < 4; ++mi) {
            #pragma unroll
            for (int ni = 0; ni < 2; ++ni) {
                #pragma unroll
                for (int r = 0; r < 4; ++r) {
                    int il = wm + mi * 16 + erow + (r >> 1) * 8;
                    int jl = wns + ni * 8 + ecol + (r & 1);
                    int dd = (i0 + il) - (j0 + jl);
                    float val = (dd >= 0) ? sacc[mi][ni][r] * sdec[dd] : 0.0f;
                    __nv_bfloat16 hi = __float2bfloat16(val);
                    __nv_bfloat16 lo = __float2bfloat16(val - __bfloat162float(hi));
                    *(__nv_bfloat16*)(smraw + A_SHI + il * 144 + jl * 2) = hi;
                    *(__nv_bfloat16*)(smraw + A_SLO + il * 144 + jl * 2) = lo;
                }
            }
        }
        __syncthreads();   // S visible; k buffer free

        // prefetch k(jt+1) and vT(jt+1) (overlap the O-phase)
        if (jt + 1 < njt) {
            const int jn = (jt + 1) * 64;
            #pragma unroll
            for (int it = 0; it < 4; ++it) {
                int idx = tid + 256 * it;
                int row = idx >> 4, sec = idx & 15;
                size_t g = (rowb + jn + row) * HD + sec * 8;
                uint32_t so = row * 272 + sec * 16;
                cpasync16(sb + A_KHI + so, g_k_hi + g);
                cpasync16(sb + A_KLO + so, g_k_lo + g);
            }
            const uint32_t vtn = sb + (cur ? A_VT0 : A_VT1);
            #pragma unroll
            for (int it = 0; it < 4; ++it) {
                int idx = tid + 256 * it;
                int row = idx >> 3, sec = idx & 7;
                size_t g = (colb + row) * SS + n * CC + jn + sec * 8;
                uint32_t so = row * 144 + sec * 16;
                cpasync16(vtn + so, g_vT_hi + g);
                cpasync16(vtn + 18432 + so, g_vT_lo + g);
            }
            cp_commit();
        }

        // ---- O += S̃ @ v ----
        #pragma unroll
        for (int ks = 0; ks < 4; ++ks) {
            uint32_t aH[4][4], aL[4][4], bH[4][2], bL[4][2];
            const uint32_t ao = (uint32_t)(lane & 15) * 144 + (lane >> 4) * 16 + ks * 32;
            #pragma unroll
            for (int mi = 0; mi < 4; ++mi) {
                ldm_x4(aH[mi], sb + A_SHI + (wm + mi * 16) * 144 + ao);
                ldm_x4(aL[mi], sb + A_SLO + (wm + mi * 16) * 144 + ao);
            }
            const uint32_t bo = (uint32_t)(lane & 7) * 144 + ((lane >> 3) & 1) * 16 + ks * 32;
            #pragma unroll
            for (int ni = 0; ni < 4; ++ni) {
                ldm_x2(bH[ni], vtb + (wno + ni * 8) * 144 + bo);
                ldm_x2(bL[ni], vtb + 18432 + (wno + ni * 8) * 144 + bo);
            }
            #pragma unroll
            for (int mi = 0; mi < 4; ++mi)
                #pragma unroll
                for (int ni = 0; ni < 4; ++ni)
                    mma16816(oacc[mi][ni], aH[mi], bH[ni]);
            #pragma unroll
            for (int mi = 0; mi < 4; ++mi)
                #pragma unroll
                for (int ni = 0; ni < 4; ++ni)
                    mma16816(oacc[mi][ni], aH[mi], bL[ni]);
            #pragma unroll
            for (int mi = 0; mi < 4; ++mi)
                #pragma unroll
                for (int ni = 0; ni < 4; ++ni)
                    mma16816(oacc[mi][ni], aL[mi], bH[ni]);
        }
    }

    // ---- epilogue: gate-fused split store to gahi/galo ----
    #pragma unroll
    for (int mi = 0; mi < 4; ++mi) {
        #pragma unroll
        for (int ni = 0; ni < 4; ++ni) {
            int il = wm + mi * 16 + erow;
            int e  = wno + ni * 8 + ecol;
            size_t o0 = (size_t)(b * SS + n * CC + i0 + il) * HIDN + h * HD + e;
            size_t o1 = o0 + 8 * HIDN;
            float2 g0 = *(const float2*)(g_gate + o0);
            float2 g1 = *(const float2*)(g_gate + o1);
            float v0 = oacc[mi][ni][0] * g0.x;
            float v1 = oacc[mi][ni][1] * g0.y;
            float v2 = oacc[mi][ni][2] * g1.x;
            float v3 = oacc[mi][ni][3] * g1.y;
            __nv_bfloat16 h0 = __float2bfloat16(v0), h1b = __float2bfloat16(v1);
            __nv_bfloat16 h2 = __float2bfloat16(v2), h3b = __float2bfloat16(v3);
            *(__nv_bfloat162*)(g_gahi + o0) = __halves2bfloat162(h0, h1b);
            *(__nv_bfloat162*)(g_gahi + o1) = __halves2bfloat162(h2, h3b);
            *(__nv_bfloat162*)(g_galo + o0) = __halves2bfloat162(
                __float2bfloat16(v0 - __bfloat162float(h0)),
                __float2bfloat16(v1 - __bfloat162float(h1b)));
            *(__nv_bfloat162*)(g_galo + o1) = __halves2bfloat162(
                __float2bfloat16(v2 - __bfloat162float(h2)),
                __float2bfloat16(v3 - __bfloat162float(h3b)));
        }
    }
}

// ---------------- launch ----------------
extern "C" void kernel_launch(void* const* d_in, const int* in_sizes, int n_in,
                              void* d_out, int out_size)
{
    const float* x      = (const float*)d_in[0];
    const float* w_qkv  = (const float*)d_in[1];
    const float* w_gate = (const float*)d_in[2];
    const float* w_out  = (const float*)d_in[3];
    const float* slopes = (const float*)d_in[4];
    float* out = (float*)d_out;

    float *qkv_p, *gate_p;
    cudaGetSymbolAddress((void**)&qkv_p,  g_qkv);
    cudaGetSymbolAddress((void**)&gate_p, g_gate);

    __nv_bfloat16 *xhi, *xlo, *wqh, *wql, *wgh, *wgl, *woh, *wol, *gah, *gal;
    cudaGetSymbolAddress((void**)&xhi, g_xhi);
    cudaGetSymbolAddress((void**)&xlo, g_xlo);
    cudaGetSymbolAddress((void**)&wqh, g_wqkvT_hi);
    cudaGetSymbolAddress((void**)&wql, g_wqkvT_lo);
    cudaGetSymbolAddress((void**)&wgh, g_wgateT_hi);
    cudaGetSymbolAddress((void**)&wgl, g_wgateT_lo);
    cudaGetSymbolAddress((void**)&woh, g_woutT_hi);
    cudaGetSymbolAddress((void**)&wol, g_woutT_lo);
    cudaGetSymbolAddress((void**)&gah, g_gahi);
    cudaGetSymbolAddress((void**)&gal, g_galo);

    cudaFuncSetAttribute(mma_gemm<EPI_SILU>,
                         cudaFuncAttributeMaxDynamicSharedMemorySize, GEMM_SMEM);
    cudaFuncSetAttribute(mma_gemm<EPI_SIGMOID>,
                         cudaFuncAttributeMaxDynamicSharedMemorySize, GEMM_SMEM);
    cudaFuncSetAttribute(mma_gemm<EPI_NONE>,
                         cudaFuncAttributeMaxDynamicSharedMemorySize, GEMM_SMEM);
    cudaFuncSetAttribute(attn_mma,
                         cudaFuncAttributeMaxDynamicSharedMemorySize, A_SMEM);
    cudaFuncSetAttribute(kvdelta_mma,
                         cudaFuncAttributeMaxDynamicSharedMemorySize, KD_SMEM);

    // 0) splits + transposes + decay tables
    {
        int n4 = MM * HIDN / 4;
        split_kernel<<<n4 / 256, 256>>>(x, xhi, xlo, n4);
        dim3 blk(32, 8);
        transp_split_kernel<<<dim3(QKVN / 32, HIDN / 32), blk>>>(w_qkv,  wqh, wql, HIDN, QKVN);
        transp_split_kernel<<<dim3(HIDN / 32, HIDN / 32), blk>>>(w_gate, wgh, wgl, HIDN, HIDN);
        transp_split_kernel<<<dim3(HIDN / 32, HIDN / 32), blk>>>(w_out,  woh, wol, HIDN, HIDN);
        dectab_kernel<<<NH, CC>>>(slopes);
    }
    // 1) qkv = silu(x @ w_qkv)
    mma_gemm<EPI_SILU><<<dim3(QKVN / 128, MM / 128), 256, GEMM_SMEM>>>(
        xhi, xlo, wqh, wql, qkv_p, MM, QKVN);
    // 2) per-head splits
    splitqkv_norm<<<(BB * SS * NH * 32) / 256, 256>>>();
    {
        dim3 blk(32, 8);
        trans_split_head<<<dim3(SS / 32, HD / 32, BB * NH), blk>>>();
    }
    // 3) gate = sigmoid(x @ w_gate)
    mma_gemm<EPI_SIGMOID><<<dim3(HIDN / 128, MM / 128), 256, GEMM_SMEM>>>(
        xhi, xlo, wgh, wgl, gate_p, MM, HIDN);
    // 4) attention pipeline
    kvdelta_mma<<<BB * NH * NCC, 256, KD_SMEM>>>();
    scan_kernel<<<BB * NH * 64, 256>>>(slopes);
    {
        dim3 blk(32, 8);
        kvsplitT_kernel<<<dim3(HD / 32, HD / 32, BB * NH * NCC), blk>>>();
    }
    attn_mma<<<dim3(BB * NH * NCC, 2), 256, A_SMEM>>>(slopes);
    // 5) out = (gate*attn) @ w_out   (gate fused into attn epilogue)
    mma_gemm<EPI_NONE><<<dim3(HIDN / 128, MM / 128), 256, GEMM_SMEM>>>(
        gah, gal, woh, wol, out, MM, HIDN);
}